// round 10
// baseline (speedup 1.0000x reference)
#include <cuda_runtime.h>
#include <cuda_bf16.h>
#include <cstddef>
#include <cstdint>

#define Bn 4
#define Cn 256
#define Ln 8000
#define CRn 64
#define Kn 7
#define Nn 24
#define EPSf 1e-5f

#define NMAT 50              // 24 main + 24 skip + init(48) + post(49)
#define WELEM 65536          // 256x256 weights per matrix
#define GEMM_SMEM 102400     // 2 stages x (A 40960 + B 10240)
#define KERN_SMEM 36864
#define INVO_SMEM 71936

// ---------------- scratch (device globals; no allocation allowed) ----------
__device__ float g_buf0[(size_t)Bn * Cn * Ln];
__device__ float g_buf1[(size_t)Bn * Cn * Ln];
__device__ float g_h[(size_t)Bn * Cn * Ln];
__device__ float g_skip[(size_t)Bn * Cn * Ln];
__device__ float g_kern[(size_t)Bn * Kn * Ln];
__device__ float g_tmp[(size_t)Bn * Cn * Ln];
__device__ __nv_bfloat16 g_whi[(size_t)NMAT * WELEM];
__device__ __nv_bfloat16 g_wlo[(size_t)NMAT * WELEM];
__device__ __nv_bfloat16 g_wrhi[(size_t)Nn * CRn * Cn];
__device__ __nv_bfloat16 g_wrlo[(size_t)Nn * CRn * Cn];

// ---------------- small helpers ---------------------------------------------
__device__ __forceinline__ uint32_t smem_u32(const void* p) {
    uint32_t a;
    asm("{ .reg .u64 t; cvta.to.shared.u64 t, %1; cvt.u32.u64 %0, t; }"
        : "=r"(a) : "l"(p));
    return a;
}
__device__ __forceinline__ void ldm4(uint32_t* r, uint32_t addr) {
    asm volatile("ldmatrix.sync.aligned.m8n8.x4.shared.b16 {%0,%1,%2,%3}, [%4];"
                 : "=r"(r[0]), "=r"(r[1]), "=r"(r[2]), "=r"(r[3]) : "r"(addr));
}
__device__ __forceinline__ void mma16816(float* c, const uint32_t* a,
                                         uint32_t b0, uint32_t b1) {
    asm volatile(
        "mma.sync.aligned.m16n8k16.row.col.f32.bf16.bf16.f32 "
        "{%0,%1,%2,%3}, {%4,%5,%6,%7}, {%8,%9}, {%10,%11,%12,%13};"
        : "=f"(c[0]), "=f"(c[1]), "=f"(c[2]), "=f"(c[3])
        : "r"(a[0]), "r"(a[1]), "r"(a[2]), "r"(a[3]), "r"(b0), "r"(b1),
          "f"(c[0]), "f"(c[1]), "f"(c[2]), "f"(c[3]));
}
__device__ __forceinline__ uint32_t pack_bf16x2(float x0, float x1) {
    __nv_bfloat16 h0 = __float2bfloat16_rn(x0);
    __nv_bfloat16 h1 = __float2bfloat16_rn(x1);
    return (uint32_t)__bfloat16_as_ushort(h0)
         | ((uint32_t)__bfloat16_as_ushort(h1) << 16);
}
__device__ __forceinline__ void cp16(uint32_t dst, const void* src) {
    asm volatile("cp.async.cg.shared.global [%0], [%1], 16;"
                 :: "r"(dst), "l"(src));
}
#define CP_COMMIT() asm volatile("cp.async.commit_group;" ::: "memory")

// ---------------- weight prep: fp32 -> bf16 hi/lo tiles ---------------------
// layout per matrix: idx = kc*8192 + row*32 + kk  (8 K-chunks of 32)
__global__ __launch_bounds__(256) void prep_kernel(
    const float* __restrict__ mw, const float* __restrict__ swp,
    const float* __restrict__ iw, const float* __restrict__ pw)
{
    int mat = blockIdx.x, seg = blockIdx.y;
    const float* W = (mat < 24) ? mw + (size_t)mat * Cn * Cn
                   : (mat < 48) ? swp + (size_t)(mat - 24) * Cn * Cn
                   : (mat == 48) ? iw : pw;
    size_t base = (size_t)mat * WELEM;
    for (int idx = seg * 8192 + threadIdx.x; idx < (seg + 1) * 8192; idx += 256) {
        int kk = idx & 31, row = (idx >> 5) & 255, kc = idx >> 13;
        float w = W[(size_t)row * Cn + kc * 32 + kk];
        __nv_bfloat16 hi = __float2bfloat16_rn(w);
        __nv_bfloat16 lo = __float2bfloat16_rn(w - __bfloat162float(hi));
        g_whi[base + idx] = hi;
        g_wlo[base + idx] = lo;
    }
}

// wr prep: per matrix 64x256, layout idx = kc*4096 + row*64 + kk (kc64 chunks)
__global__ __launch_bounds__(256) void prep_wr(const float* __restrict__ wr_all)
{
    int mat = blockIdx.x;
    const float* W = wr_all + (size_t)mat * CRn * Cn;
    size_t base = (size_t)mat * CRn * Cn;
    for (int idx = threadIdx.x; idx < CRn * Cn; idx += 256) {
        int kk = idx & 63, row = (idx >> 6) & 63, kc = idx >> 12;
        float w = W[(size_t)row * Cn + kc * 64 + kk];
        __nv_bfloat16 hi = __float2bfloat16_rn(w);
        __nv_bfloat16 lo = __float2bfloat16_rn(w - __bfloat162float(hi));
        g_wrhi[base + idx] = hi;
        g_wrlo[base + idx] = lo;
    }
}

// ---------------- zero ------------------------------------------------------
__global__ void zero_kernel(float* p, size_t n) {
    size_t i = (size_t)blockIdx.x * blockDim.x + threadIdx.x;
    if (i < n) p[i] = 0.f;
}

// ---------------- channel LayerNorm (over C) --------------------------------
__global__ __launch_bounds__(256) void ln_kernel(
    const float* __restrict__ x, const float* __restrict__ g,
    const float* __restrict__ bta, float* __restrict__ y)
{
    int b = blockIdx.y, lbase = blockIdx.x * 32;
    int t = threadIdx.x, j = t & 31, cg = t >> 5;
    __shared__ float vs[Cn][32];
    __shared__ float psum[8][32], psq[8][32];
    __shared__ float mres[32], rres[32];

    const float* xb = x + ((size_t)b * Cn) * Ln + lbase;
    float s = 0.f, sq = 0.f;
#pragma unroll 4
    for (int i = 0; i < 32; i++) {
        int c = cg * 32 + i;
        float v = xb[(size_t)c * Ln + j];
        vs[c][j] = v; s += v; sq += v * v;
    }
    psum[cg][j] = s; psq[cg][j] = sq;
    __syncthreads();
    if (t < 32) {
        float S = 0.f, Q = 0.f;
#pragma unroll
        for (int i = 0; i < 8; i++) { S += psum[i][t]; Q += psq[i][t]; }
        float m = S * (1.f / Cn);
        float var = Q * (1.f / Cn) - m * m;
        mres[t] = m; rres[t] = rsqrtf(var + EPSf);
    }
    __syncthreads();
    float m = mres[j], r = rres[j];
    float* yb = y + ((size_t)b * Cn) * Ln + lbase;
#pragma unroll 4
    for (int i = 0; i < 32; i++) {
        int c = cg * 32 + i;
        yb[(size_t)c * Ln + j] = (vs[c][j] - m) * r * g[c] + bta[c];
    }
}

// ---------------- involution kernel generator (HMMA) ------------------------
__global__ __launch_bounds__(256) void kern_mma(
    const float* __restrict__ out, const float* __restrict__ ws,
    int mat, float* __restrict__ kern)
{
    extern __shared__ char ksm[];
    uint16_t* Ahi = (uint16_t*)ksm;        // 64 x 72
    uint16_t* Alo = Ahi + 64 * 72;         // 64 x 72
    uint16_t* Bhi = Alo + 64 * 72;         // 64 x 72 (rows = positions)
    uint16_t* Blo = Bhi + 64 * 72;         // 64 x 72
    float* rs = (float*)ksm;               // aliased after mma: 64 x 65

    int t = threadIdx.x, lid = t & 31, wid = t >> 5;
    int wm = wid >> 2, wn = wid & 3;       // 2 M-warps x 4 N-warps
    int b = blockIdx.y, lbase = blockIdx.x * 64;
    const float* Xb = out + (size_t)b * Cn * Ln + lbase;
    const __nv_bfloat16* Wh = g_wrhi + (size_t)mat * CRn * Cn;
    const __nv_bfloat16* Wl = g_wrlo + (size_t)mat * CRn * Cn;

    float acc[2][2][4];
#pragma unroll
    for (int i = 0; i < 2; i++)
#pragma unroll
        for (int jx = 0; jx < 2; jx++)
#pragma unroll
            for (int p = 0; p < 4; p++) acc[i][jx][p] = 0.f;

    int lr   = (lid & 7) + ((lid >> 3) & 1) * 8;
    int koff = (lid >> 4) * 8;
    uint32_t sbase = smem_u32(ksm);

    for (int kc = 0; kc < 4; kc++) {
        {
            const float4* shi = (const float4*)(Wh + kc * 4096);
            const float4* slo = (const float4*)(Wl + kc * 4096);
#pragma unroll
            for (int m = 0; m < 2; m++) {
                int i = m * 256 + t;
                int row = i >> 3, q = i & 7;
                *(float4*)(Ahi + row * 72 + q * 8) = shi[i];
                *(float4*)(Alo + row * 72 + q * 8) = slo[i];
            }
        }
        {
            int pos = t & 63, kp = t >> 6;
#pragma unroll
            for (int it = 0; it < 8; it++) {
                int k2 = (kp + it * 4) * 2;
                float x0 = Xb[(size_t)(kc * 64 + k2) * Ln + pos];
                float x1 = Xb[(size_t)(kc * 64 + k2 + 1) * Ln + pos];
                __nv_bfloat16 h0 = __float2bfloat16_rn(x0);
                __nv_bfloat16 h1 = __float2bfloat16_rn(x1);
                *(uint32_t*)(Bhi + pos * 72 + k2) =
                    (uint32_t)__bfloat16_as_ushort(h0)
                  | ((uint32_t)__bfloat16_as_ushort(h1) << 16);
                *(uint32_t*)(Blo + pos * 72 + k2) =
                    pack_bf16x2(x0 - __bfloat162float(h0),
                                x1 - __bfloat162float(h1));
            }
        }
        __syncthreads();

#pragma unroll
        for (int ks = 0; ks < 4; ks++) {
            int kcol = ks * 16 + koff;
            uint32_t bh[4], bl[4];
            uint32_t bb = sbase + 2 * (2 * 64 * 72);
            ldm4(bh, bb + (uint32_t)(((wn * 16 + lr) * 72 + kcol) * 2));
            ldm4(bl, bb + 64 * 72 * 2
                     + (uint32_t)(((wn * 16 + lr) * 72 + kcol) * 2));
#pragma unroll
            for (int mt = 0; mt < 2; mt++) {
                uint32_t ah[4], al[4];
                int arow = wm * 32 + mt * 16 + lr;
                ldm4(ah, sbase + (uint32_t)((arow * 72 + kcol) * 2));
                ldm4(al, sbase + 64 * 72 * 2
                         + (uint32_t)((arow * 72 + kcol) * 2));
                mma16816(acc[mt][0], ah, bh[0], bh[2]);
                mma16816(acc[mt][0], ah, bl[0], bl[2]);
                mma16816(acc[mt][0], al, bh[0], bh[2]);
                mma16816(acc[mt][1], ah, bh[1], bh[3]);
                mma16816(acc[mt][1], ah, bl[1], bl[3]);
                mma16816(acc[mt][1], al, bh[1], bh[3]);
            }
        }
        __syncthreads();
    }

    {
        int r0 = wm * 32 + (lid >> 2), c0 = wn * 16 + (lid & 3) * 2;
#pragma unroll
        for (int mt = 0; mt < 2; mt++)
#pragma unroll
            for (int nt = 0; nt < 2; nt++)
#pragma unroll
                for (int half = 0; half < 2; half++) {
                    int r = r0 + mt * 16 + half * 8;
                    int c = c0 + nt * 8;
                    rs[r * 65 + c]     = fmaxf(acc[mt][nt][half * 2 + 0], 0.f);
                    rs[r * 65 + c + 1] = fmaxf(acc[mt][nt][half * 2 + 1], 0.f);
                }
    }
    __syncthreads();

    for (int kk = t; kk < Kn * 64; kk += 256) {
        int k = kk >> 6, j = kk & 63;
        float a = 0.f;
        const float* wsk = ws + (size_t)k * CRn;
#pragma unroll 8
        for (int r2 = 0; r2 < CRn; r2++) a += wsk[r2] * rs[r2 * 65 + j];
        kern[((size_t)b * Kn + k) * Ln + lbase + j] = a;
    }
}

// ---------------- involution apply + PReLU + channel LN (64-pos, float2) ----
__global__ __launch_bounds__(256) void invo_kernel(
    const float* __restrict__ out, const float* __restrict__ kern,
    const float* __restrict__ pa, const float* __restrict__ g,
    const float* __restrict__ bta, int dil, float* __restrict__ h)
{
    extern __shared__ float ism[];
    float* hs   = ism;            // 256 x 64
    float* ks   = ism + 16384;    // 7 x 64
    float* psum = ks + 448;       // 8 x 64
    float* psq  = psum + 512;     // 8 x 64
    float* mres = psq + 512;      // 64
    float* rres = mres + 64;      // 64

    int b = blockIdx.y, lbase = blockIdx.x * 64;
    int t = threadIdx.x, jj = t & 31, cg = t >> 5;

    for (int i = t; i < Kn * 64; i += 256)
        ks[i] = kern[((size_t)b * Kn + (i >> 6)) * Ln + lbase + (i & 63)];
    __syncthreads();

    float a = *pa;
    const float* ob = out + ((size_t)b * Cn) * Ln;
    int l0 = lbase + 2 * jj;
    float s0 = 0.f, q0 = 0.f, s1 = 0.f, q1 = 0.f;

#pragma unroll 2
    for (int i = 0; i < 32; i++) {
        int c = cg * 32 + i;
        const float* oc = ob + (size_t)c * Ln;
        float a0 = 0.f, a1 = 0.f;
        if (dil > 1) {
#pragma unroll
            for (int k = 0; k < Kn; k++) {
                int ll = l0 + (k - 3) * dil;
                float vx, vy;
                if (ll >= 0 && ll + 1 < Ln) {
                    float2 v = *(const float2*)&oc[ll];
                    vx = v.x; vy = v.y;
                } else {
                    vx = (ll >= 0 && ll < Ln) ? oc[ll] : 0.f;
                    int l2 = ll + 1;
                    vy = (l2 >= 0 && l2 < Ln) ? oc[l2] : 0.f;
                }
                a0 += vx * ks[k * 64 + 2 * jj];
                a1 += vy * ks[k * 64 + 2 * jj + 1];
            }
        } else {
#pragma unroll
            for (int k = 0; k < Kn; k++) {
                int ll = l0 + (k - 3);
                float vx = (ll >= 0 && ll < Ln) ? oc[ll] : 0.f;
                int l2 = ll + 1;
                float vy = (l2 >= 0 && l2 < Ln) ? oc[l2] : 0.f;
                a0 += vx * ks[k * 64 + 2 * jj];
                a1 += vy * ks[k * 64 + 2 * jj + 1];
            }
        }
        a0 = a0 >= 0.f ? a0 : a * a0;
        a1 = a1 >= 0.f ? a1 : a * a1;
        hs[c * 64 + 2 * jj]     = a0;
        hs[c * 64 + 2 * jj + 1] = a1;
        s0 += a0; q0 += a0 * a0;
        s1 += a1; q1 += a1 * a1;
    }
    psum[cg * 64 + 2 * jj]     = s0;
    psum[cg * 64 + 2 * jj + 1] = s1;
    psq[cg * 64 + 2 * jj]      = q0;
    psq[cg * 64 + 2 * jj + 1]  = q1;
    __syncthreads();
    if (t < 64) {
        float S = 0.f, Q = 0.f;
#pragma unroll
        for (int i = 0; i < 8; i++) { S += psum[i * 64 + t]; Q += psq[i * 64 + t]; }
        float m = S * (1.f / Cn);
        mres[t] = m; rres[t] = rsqrtf(Q * (1.f / Cn) - m * m + EPSf);
    }
    __syncthreads();
    float m0 = mres[2 * jj], r0 = rres[2 * jj];
    float m1 = mres[2 * jj + 1], r1 = rres[2 * jj + 1];
    float* hb = h + ((size_t)b * Cn) * Ln + lbase;
#pragma unroll 4
    for (int i = 0; i < 32; i++) {
        int c = cg * 32 + i;
        float gg = g[c], bb = bta[c];
        float2 v;
        v.x = (hs[c * 64 + 2 * jj]     - m0) * r0 * gg + bb;
        v.y = (hs[c * 64 + 2 * jj + 1] - m1) * r1 * gg + bb;
        *(float2*)&hb[(size_t)c * Ln + 2 * jj] = v;
    }
}

// ---------------- HMMA bf16-split GEMM, cp.async double-buffered ------------
// K=256 in 8 chunks of 32, 2-stage pipeline. Per stage: A 256x40 hi+lo
// (40960 B), B 64x40 hi+lo (10240 B). launch_bounds(256,2).
// mode 0: Y = D   1: Y = D + R   2: Y += D   3: Y = relu(D), X prelu'd on load.
__global__ __launch_bounds__(256, 2) void gemm_mma(
    const float* __restrict__ X, const float* __restrict__ R,
    float* __restrict__ Y, int mat, const float* __restrict__ pa, int mode)
{
    extern __shared__ char smem[];
    uint32_t sb = smem_u32(smem);

    int t = threadIdx.x, lid = t & 31, wid = t >> 5;
    int wm = wid >> 1, wn = wid & 1;          // 4 M-warps x 2 N-warps
    int b = blockIdx.y, lbase = blockIdx.x * 64;

    const float* Xb = X + (size_t)b * Cn * Ln + lbase;
    float aP = (mode == 3) ? *pa : 0.f;

    const __nv_bfloat16* Whb = g_whi + (size_t)mat * WELEM;
    const __nv_bfloat16* Wlb = g_wlo + (size_t)mat * WELEM;

    float acc[4][4][4];
#pragma unroll
    for (int i = 0; i < 4; i++)
#pragma unroll
        for (int jx = 0; jx < 4; jx++)
#pragma unroll
            for (int p = 0; p < 4; p++) acc[i][jx][p] = 0.f;

    int lr   = (lid & 7) + ((lid >> 3) & 1) * 8;
    int koff = (lid >> 4) * 8;

    // ---- stage helpers (inlined via lambdas) ----
    auto stageA = [&](int kc, int s) {
        const char* srcH = (const char*)(Whb + kc * 8192);
        const char* srcL = (const char*)(Wlb + kc * 8192);
        uint32_t dstH = sb + s * 40960;
        uint32_t dstL = dstH + 20480;
#pragma unroll
        for (int m = 0; m < 4; m++) {
            int i = m * 256 + t;              // 16B unit, 0..1023
            int row = i >> 2, q = i & 3;
            uint32_t dof = (uint32_t)(row * 80 + q * 16);
            cp16(dstH + dof, srcH + i * 16);
            cp16(dstL + dof, srcL + i * 16);
        }
    };
    auto stageB = [&](int kc, int s) {
        uint16_t* Bh = (uint16_t*)(smem + 81920 + s * 10240);
        uint16_t* Bl = Bh + 2560;             // 5120 bytes
        int pos = t & 63, kp = t >> 6;
#pragma unroll
        for (int it = 0; it < 4; it++) {
            int k2 = (kp + it * 4) * 2;       // 0..30
            float x0 = Xb[(size_t)(kc * 32 + k2) * Ln + pos];
            float x1 = Xb[(size_t)(kc * 32 + k2 + 1) * Ln + pos];
            if (mode == 3) {
                x0 = x0 >= 0.f ? x0 : aP * x0;
                x1 = x1 >= 0.f ? x1 : aP * x1;
            }
            __nv_bfloat16 h0 = __float2bfloat16_rn(x0);
            __nv_bfloat16 h1 = __float2bfloat16_rn(x1);
            *(uint32_t*)(Bh + pos * 40 + k2) =
                (uint32_t)__bfloat16_as_ushort(h0)
              | ((uint32_t)__bfloat16_as_ushort(h1) << 16);
            *(uint32_t*)(Bl + pos * 40 + k2) =
                pack_bf16x2(x0 - __bfloat162float(h0),
                            x1 - __bfloat162float(h1));
        }
    };

    // prologue: chunk 0
    stageA(0, 0); CP_COMMIT(); stageB(0, 0);

    for (int kc = 0; kc < 8; kc++) {
        int s = kc & 1;
        if (kc < 7) {
            stageA(kc + 1, s ^ 1); CP_COMMIT();
            stageB(kc + 1, s ^ 1);
            asm volatile("cp.async.wait_group 1;" ::: "memory");
        } else {
            asm volatile("cp.async.wait_group 0;" ::: "memory");
        }
        __syncthreads();

        uint32_t aH = sb + s * 40960;
        uint32_t aL = aH + 20480;
        uint32_t bH = sb + 81920 + s * 10240;
        uint32_t bL = bH + 5120;
#pragma unroll
        for (int ks = 0; ks < 2; ks++) {
            int kcol = ks * 16 + koff;
            uint32_t bh0[4], bh1[4], bl0[4], bl1[4];
            ldm4(bh0, bH + (uint32_t)(((wn * 32 + lr) * 40 + kcol) * 2));
            ldm4(bh1, bH + (uint32_t)(((wn * 32 + 16 + lr) * 40 + kcol) * 2));
            ldm4(bl0, bL + (uint32_t)(((wn * 32 + lr) * 40 + kcol) * 2));
            ldm4(bl1, bL + (uint32_t)(((wn * 32 + 16 + lr) * 40 + kcol) * 2));
#pragma unroll
            for (int mt = 0; mt < 4; mt++) {
                uint32_t ah[4], al[4];
                int arow = wm * 64 + mt * 16 + lr;
                ldm4(ah, aH + (uint32_t)((arow * 40 + kcol) * 2));
                ldm4(al, aL + (uint32_t)((arow * 40 + kcol) * 2));
                mma16816(acc[mt][0], ah, bh0[0], bh0[2]);
                mma16816(acc[mt][0], ah, bl0[0], bl0[2]);
                mma16816(acc[mt][0], al, bh0[0], bh0[2]);
                mma16816(acc[mt][1], ah, bh0[1], bh0[3]);
                mma16816(acc[mt][1], ah, bl0[1], bl0[3]);
                mma16816(acc[mt][1], al, bh0[1], bh0[3]);
                mma16816(acc[mt][2], ah, bh1[0], bh1[2]);
                mma16816(acc[mt][2], ah, bl1[0], bl1[2]);
                mma16816(acc[mt][2], al, bh1[0], bh1[2]);
                mma16816(acc[mt][3], ah, bh1[1], bh1[3]);
                mma16816(acc[mt][3], ah, bl1[1], bl1[3]);
                mma16816(acc[mt][3], al, bh1[1], bh1[3]);
            }
        }
        __syncthreads();
    }

    // ---- epilogue: direct float2 stores ----
    int rbase = wm * 64 + (lid >> 2);
    int cbase = wn * 32 + (lid & 3) * 2;
#pragma unroll
    for (int mt = 0; mt < 4; mt++) {
#pragma unroll
        for (int nt = 0; nt < 4; nt++) {
            int c0 = cbase + nt * 8;
#pragma unroll
            for (int half = 0; half < 2; half++) {
                int r0 = rbase + mt * 16 + half * 8;
                float vx = acc[mt][nt][half * 2 + 0];
                float vy = acc[mt][nt][half * 2 + 1];
                float* yp = Y + ((size_t)(b * Cn + r0)) * Ln + lbase + c0;
                if (mode == 1) {
                    const float2 rv = *(const float2*)
                        (R + ((size_t)(b * Cn + r0)) * Ln + lbase + c0);
                    vx += rv.x; vy += rv.y;
                } else if (mode == 2) {
                    float2 cur = *(float2*)yp;
                    vx += cur.x; vy += cur.y;
                } else if (mode == 3) {
                    vx = fmaxf(vx, 0.f); vy = fmaxf(vy, 0.f);
                }
                float2 o; o.x = vx; o.y = vy;
                *(float2*)yp = o;
            }
        }
    }
}

// ---------------- launcher ---------------------------------------------------
extern "C" void kernel_launch(void* const* d_in, const int* in_sizes, int n_in,
                              void* d_out, int out_size)
{
    const float* x           = (const float*)d_in[0];
    const float* init_ln_g   = (const float*)d_in[1];
    const float* init_ln_b   = (const float*)d_in[2];
    const float* init_conv_w = (const float*)d_in[3];
    const float* w_reduce    = (const float*)d_in[4];
    const float* w_span      = (const float*)d_in[5];
    const float* prelu_a     = (const float*)d_in[6];
    const float* ln_g        = (const float*)d_in[7];
    const float* ln_b        = (const float*)d_in[8];
    const float* conv_main_w = (const float*)d_in[9];
    const float* conv_skip_w = (const float*)d_in[10];
    const float* post_prelu  = (const float*)d_in[11];
    const float* post_conv_w = (const float*)d_in[12];

    float *buf0, *buf1, *hbuf, *skip, *kern, *tmp;
    cudaGetSymbolAddress((void**)&buf0, g_buf0);
    cudaGetSymbolAddress((void**)&buf1, g_buf1);
    cudaGetSymbolAddress((void**)&hbuf, g_h);
    cudaGetSymbolAddress((void**)&skip, g_skip);
    cudaGetSymbolAddress((void**)&kern, g_kern);
    cudaGetSymbolAddress((void**)&tmp,  g_tmp);

    cudaFuncSetAttribute(gemm_mma, cudaFuncAttributeMaxDynamicSharedMemorySize,
                         GEMM_SMEM);
    cudaFuncSetAttribute(invo_kernel, cudaFuncAttributeMaxDynamicSharedMemorySize,
                         INVO_SMEM);

    dim3 g32(Ln / 32, Bn);
    dim3 g64(Ln / 64, Bn);
    size_t nelem = (size_t)Bn * Cn * Ln;

    zero_kernel<<<(int)((nelem + 1023) / 1024), 1024>>>(skip, nelem);
    prep_kernel<<<dim3(NMAT, 8), 256>>>(conv_main_w, conv_skip_w,
                                        init_conv_w, post_conv_w);
    prep_wr<<<Nn, 256>>>(w_reduce);
    ln_kernel<<<g32, 256>>>(x, init_ln_g, init_ln_b, tmp);

    // init conv: mat 48, mode 0
    gemm_mma<<<g64, 256, GEMM_SMEM>>>(tmp, nullptr, buf0, 48, nullptr, 0);

    float* out  = buf0;
    float* outn = buf1;
    for (int i = 0; i < Nn; i++) {
        int d = 1 << (i & 7);
        kern_mma<<<g64, 256, KERN_SMEM>>>(out, w_span + (size_t)i * Kn * CRn,
                                          i, kern);
        invo_kernel<<<g64, 256, INVO_SMEM>>>(out, kern, prelu_a + i,
                                  ln_g + (size_t)i * Cn, ln_b + (size_t)i * Cn, d, hbuf);
        gemm_mma<<<g64, 256, GEMM_SMEM>>>(hbuf, out, outn, i, nullptr, 1);
        gemm_mma<<<g64, 256, GEMM_SMEM>>>(hbuf, nullptr, skip, 24 + i, nullptr, 2);
        float* tsw = out; out = outn; outn = tsw;
    }

    // post: prelu -> conv -> relu
    gemm_mma<<<g64, 256, GEMM_SMEM>>>(skip, nullptr, (float*)d_out, 49, post_prelu, 3);
}

// round 11
// speedup vs baseline: 1.5410x; 1.5410x over previous
#include <cuda_runtime.h>
#include <cuda_bf16.h>
#include <cstddef>
#include <cstdint>

#define Bn 4
#define Cn 256
#define Ln 8000
#define CRn 64
#define Kn 7
#define Nn 24
#define EPSf 1e-5f

#define NMAT 50              // 24 main + 24 skip + init(48) + post(49)
#define WELEM 65536          // 256x256 weights per matrix
#define GEMM_SMEM 92160      // bytes of dynamic smem for gemm_mma
#define KERN_SMEM 36864
#define INVO_SMEM 71936

// ---------------- scratch (device globals; no allocation allowed) ----------
__device__ float g_buf0[(size_t)Bn * Cn * Ln];
__device__ float g_buf1[(size_t)Bn * Cn * Ln];
__device__ float g_h[(size_t)Bn * Cn * Ln];
__device__ float g_skip[(size_t)Bn * Cn * Ln];
__device__ float g_kern[(size_t)Bn * Kn * Ln];
__device__ float g_tmp[(size_t)Bn * Cn * Ln];
__device__ __nv_bfloat16 g_whi[(size_t)NMAT * WELEM];
__device__ __nv_bfloat16 g_wlo[(size_t)NMAT * WELEM];
__device__ __nv_bfloat16 g_wrhi[(size_t)Nn * CRn * Cn];
__device__ __nv_bfloat16 g_wrlo[(size_t)Nn * CRn * Cn];

// ---------------- small helpers ---------------------------------------------
__device__ __forceinline__ uint32_t smem_u32(const void* p) {
    uint32_t a;
    asm("{ .reg .u64 t; cvta.to.shared.u64 t, %1; cvt.u32.u64 %0, t; }"
        : "=r"(a) : "l"(p));
    return a;
}
__device__ __forceinline__ void ldm4(uint32_t* r, uint32_t addr) {
    asm volatile("ldmatrix.sync.aligned.m8n8.x4.shared.b16 {%0,%1,%2,%3}, [%4];"
                 : "=r"(r[0]), "=r"(r[1]), "=r"(r[2]), "=r"(r[3]) : "r"(addr));
}
__device__ __forceinline__ void mma16816(float* c, const uint32_t* a,
                                         uint32_t b0, uint32_t b1) {
    asm volatile(
        "mma.sync.aligned.m16n8k16.row.col.f32.bf16.bf16.f32 "
        "{%0,%1,%2,%3}, {%4,%5,%6,%7}, {%8,%9}, {%10,%11,%12,%13};"
        : "=f"(c[0]), "=f"(c[1]), "=f"(c[2]), "=f"(c[3])
        : "r"(a[0]), "r"(a[1]), "r"(a[2]), "r"(a[3]), "r"(b0), "r"(b1),
          "f"(c[0]), "f"(c[1]), "f"(c[2]), "f"(c[3]));
}
__device__ __forceinline__ uint32_t pack_bf16x2(float x0, float x1) {
    __nv_bfloat16 h0 = __float2bfloat16_rn(x0);
    __nv_bfloat16 h1 = __float2bfloat16_rn(x1);
    return (uint32_t)__bfloat16_as_ushort(h0)
         | ((uint32_t)__bfloat16_as_ushort(h1) << 16);
}

// ---------------- weight prep: fp32 -> bf16 hi/lo tiles ---------------------
// layout per matrix: idx = kc*16384 + row*64 + kk, W element [row][kc*64+kk]
__global__ __launch_bounds__(256) void prep_kernel(
    const float* __restrict__ mw, const float* __restrict__ swp,
    const float* __restrict__ iw, const float* __restrict__ pw)
{
    int mat = blockIdx.x, seg = blockIdx.y;
    const float* W = (mat < 24) ? mw + (size_t)mat * Cn * Cn
                   : (mat < 48) ? swp + (size_t)(mat - 24) * Cn * Cn
                   : (mat == 48) ? iw : pw;
    size_t base = (size_t)mat * WELEM;
    for (int idx = seg * 8192 + threadIdx.x; idx < (seg + 1) * 8192; idx += 256) {
        int kk = idx & 63, row = (idx >> 6) & 255, kc = idx >> 14;
        float w = W[(size_t)row * Cn + kc * 64 + kk];
        __nv_bfloat16 hi = __float2bfloat16_rn(w);
        __nv_bfloat16 lo = __float2bfloat16_rn(w - __bfloat162float(hi));
        g_whi[base + idx] = hi;
        g_wlo[base + idx] = lo;
    }
}

// wr prep: per matrix 64x256, layout idx = kc*4096 + row*64 + kk
__global__ __launch_bounds__(256) void prep_wr(const float* __restrict__ wr_all)
{
    int mat = blockIdx.x;
    const float* W = wr_all + (size_t)mat * CRn * Cn;
    size_t base = (size_t)mat * CRn * Cn;
    for (int idx = threadIdx.x; idx < CRn * Cn; idx += 256) {
        int kk = idx & 63, row = (idx >> 6) & 63, kc = idx >> 12;
        float w = W[(size_t)row * Cn + kc * 64 + kk];
        __nv_bfloat16 hi = __float2bfloat16_rn(w);
        __nv_bfloat16 lo = __float2bfloat16_rn(w - __bfloat162float(hi));
        g_wrhi[base + idx] = hi;
        g_wrlo[base + idx] = lo;
    }
}

// ---------------- zero ------------------------------------------------------
__global__ void zero_kernel(float* p, size_t n) {
    size_t i = (size_t)blockIdx.x * blockDim.x + threadIdx.x;
    if (i < n) p[i] = 0.f;
}

// ---------------- channel LayerNorm (over C) --------------------------------
__global__ __launch_bounds__(256) void ln_kernel(
    const float* __restrict__ x, const float* __restrict__ g,
    const float* __restrict__ bta, float* __restrict__ y)
{
    int b = blockIdx.y, lbase = blockIdx.x * 32;
    int t = threadIdx.x, j = t & 31, cg = t >> 5;
    __shared__ float vs[Cn][32];
    __shared__ float psum[8][32], psq[8][32];
    __shared__ float mres[32], rres[32];

    const float* xb = x + ((size_t)b * Cn) * Ln + lbase;
    float s = 0.f, sq = 0.f;
#pragma unroll 4
    for (int i = 0; i < 32; i++) {
        int c = cg * 32 + i;
        float v = xb[(size_t)c * Ln + j];
        vs[c][j] = v; s += v; sq += v * v;
    }
    psum[cg][j] = s; psq[cg][j] = sq;
    __syncthreads();
    if (t < 32) {
        float S = 0.f, Q = 0.f;
#pragma unroll
        for (int i = 0; i < 8; i++) { S += psum[i][t]; Q += psq[i][t]; }
        float m = S * (1.f / Cn);
        float var = Q * (1.f / Cn) - m * m;
        mres[t] = m; rres[t] = rsqrtf(var + EPSf);
    }
    __syncthreads();
    float m = mres[j], r = rres[j];
    float* yb = y + ((size_t)b * Cn) * Ln + lbase;
#pragma unroll 4
    for (int i = 0; i < 32; i++) {
        int c = cg * 32 + i;
        yb[(size_t)c * Ln + j] = (vs[c][j] - m) * r * g[c] + bta[c];
    }
}

// ---------------- involution kernel generator (HMMA) ------------------------
__global__ __launch_bounds__(256) void kern_mma(
    const float* __restrict__ out, const float* __restrict__ ws,
    int mat, float* __restrict__ kern)
{
    extern __shared__ char ksm[];
    uint16_t* Ahi = (uint16_t*)ksm;        // 64 x 72
    uint16_t* Alo = Ahi + 64 * 72;         // 64 x 72
    uint16_t* Bhi = Alo + 64 * 72;         // 64 x 72 (rows = positions)
    uint16_t* Blo = Bhi + 64 * 72;         // 64 x 72
    float* rs = (float*)ksm;               // aliased after mma: 64 x 65

    int t = threadIdx.x, lid = t & 31, wid = t >> 5;
    int wm = wid >> 2, wn = wid & 3;       // 2 M-warps x 4 N-warps
    int b = blockIdx.y, lbase = blockIdx.x * 64;
    const float* Xb = out + (size_t)b * Cn * Ln + lbase;
    const __nv_bfloat16* Wh = g_wrhi + (size_t)mat * CRn * Cn;
    const __nv_bfloat16* Wl = g_wrlo + (size_t)mat * CRn * Cn;

    float acc[2][2][4];
#pragma unroll
    for (int i = 0; i < 2; i++)
#pragma unroll
        for (int jx = 0; jx < 2; jx++)
#pragma unroll
            for (int p = 0; p < 4; p++) acc[i][jx][p] = 0.f;

    int lr   = (lid & 7) + ((lid >> 3) & 1) * 8;
    int koff = (lid >> 4) * 8;
    uint32_t sbase = smem_u32(ksm);

    for (int kc = 0; kc < 4; kc++) {
        {
            const float4* shi = (const float4*)(Wh + kc * 4096);
            const float4* slo = (const float4*)(Wl + kc * 4096);
#pragma unroll
            for (int m = 0; m < 2; m++) {
                int i = m * 256 + t;
                int row = i >> 3, q = i & 7;
                *(float4*)(Ahi + row * 72 + q * 8) = shi[i];
                *(float4*)(Alo + row * 72 + q * 8) = slo[i];
            }
        }
        {
            int pos = t & 63, kp = t >> 6;
#pragma unroll
            for (int it = 0; it < 8; it++) {
                int k2 = (kp + it * 4) * 2;
                float x0 = Xb[(size_t)(kc * 64 + k2) * Ln + pos];
                float x1 = Xb[(size_t)(kc * 64 + k2 + 1) * Ln + pos];
                __nv_bfloat16 h0 = __float2bfloat16_rn(x0);
                __nv_bfloat16 h1 = __float2bfloat16_rn(x1);
                *(uint32_t*)(Bhi + pos * 72 + k2) =
                    (uint32_t)__bfloat16_as_ushort(h0)
                  | ((uint32_t)__bfloat16_as_ushort(h1) << 16);
                *(uint32_t*)(Blo + pos * 72 + k2) =
                    pack_bf16x2(x0 - __bfloat162float(h0),
                                x1 - __bfloat162float(h1));
            }
        }
        __syncthreads();

#pragma unroll
        for (int ks = 0; ks < 4; ks++) {
            int kcol = ks * 16 + koff;
            uint32_t bh[4], bl[4];
            uint32_t bb = sbase + 2 * (2 * 64 * 72);
            ldm4(bh, bb + (uint32_t)(((wn * 16 + lr) * 72 + kcol) * 2));
            ldm4(bl, bb + 64 * 72 * 2
                     + (uint32_t)(((wn * 16 + lr) * 72 + kcol) * 2));
#pragma unroll
            for (int mt = 0; mt < 2; mt++) {
                uint32_t ah[4], al[4];
                int arow = wm * 32 + mt * 16 + lr;
                ldm4(ah, sbase + (uint32_t)((arow * 72 + kcol) * 2));
                ldm4(al, sbase + 64 * 72 * 2
                         + (uint32_t)((arow * 72 + kcol) * 2));
                mma16816(acc[mt][0], ah, bh[0], bh[2]);
                mma16816(acc[mt][0], ah, bl[0], bl[2]);
                mma16816(acc[mt][0], al, bh[0], bh[2]);
                mma16816(acc[mt][1], ah, bh[1], bh[3]);
                mma16816(acc[mt][1], ah, bl[1], bl[3]);
                mma16816(acc[mt][1], al, bh[1], bh[3]);
            }
        }
        __syncthreads();
    }

    {
        int r0 = wm * 32 + (lid >> 2), c0 = wn * 16 + (lid & 3) * 2;
#pragma unroll
        for (int mt = 0; mt < 2; mt++)
#pragma unroll
            for (int nt = 0; nt < 2; nt++)
#pragma unroll
                for (int half = 0; half < 2; half++) {
                    int r = r0 + mt * 16 + half * 8;
                    int c = c0 + nt * 8;
                    rs[r * 65 + c]     = fmaxf(acc[mt][nt][half * 2 + 0], 0.f);
                    rs[r * 65 + c + 1] = fmaxf(acc[mt][nt][half * 2 + 1], 0.f);
                }
    }
    __syncthreads();

    for (int kk = t; kk < Kn * 64; kk += 256) {
        int k = kk >> 6, j = kk & 63;
        float a = 0.f;
        const float* wsk = ws + (size_t)k * CRn;
#pragma unroll 8
        for (int r2 = 0; r2 < CRn; r2++) a += wsk[r2] * rs[r2 * 65 + j];
        kern[((size_t)b * Kn + k) * Ln + lbase + j] = a;
    }
}

// ---------------- involution apply + PReLU + channel LN (64-pos, float2) ----
__global__ __launch_bounds__(256) void invo_kernel(
    const float* __restrict__ out, const float* __restrict__ kern,
    const float* __restrict__ pa, const float* __restrict__ g,
    const float* __restrict__ bta, int dil, float* __restrict__ h)
{
    extern __shared__ float ism[];
    float* hs   = ism;            // 256 x 64
    float* ks   = ism + 16384;    // 7 x 64
    float* psum = ks + 448;       // 8 x 64
    float* psq  = psum + 512;     // 8 x 64
    float* mres = psq + 512;      // 64
    float* rres = mres + 64;      // 64

    int b = blockIdx.y, lbase = blockIdx.x * 64;
    int t = threadIdx.x, jj = t & 31, cg = t >> 5;

    for (int i = t; i < Kn * 64; i += 256)
        ks[i] = kern[((size_t)b * Kn + (i >> 6)) * Ln + lbase + (i & 63)];
    __syncthreads();

    float a = *pa;
    const float* ob = out + ((size_t)b * Cn) * Ln;
    int l0 = lbase + 2 * jj;
    float s0 = 0.f, q0 = 0.f, s1 = 0.f, q1 = 0.f;

#pragma unroll 2
    for (int i = 0; i < 32; i++) {
        int c = cg * 32 + i;
        const float* oc = ob + (size_t)c * Ln;
        float a0 = 0.f, a1 = 0.f;
        if (dil > 1) {
#pragma unroll
            for (int k = 0; k < Kn; k++) {
                int ll = l0 + (k - 3) * dil;
                float vx, vy;
                if (ll >= 0 && ll + 1 < Ln) {
                    float2 v = *(const float2*)&oc[ll];
                    vx = v.x; vy = v.y;
                } else {
                    vx = (ll >= 0 && ll < Ln) ? oc[ll] : 0.f;
                    int l2 = ll + 1;
                    vy = (l2 >= 0 && l2 < Ln) ? oc[l2] : 0.f;
                }
                a0 += vx * ks[k * 64 + 2 * jj];
                a1 += vy * ks[k * 64 + 2 * jj + 1];
            }
        } else {
#pragma unroll
            for (int k = 0; k < Kn; k++) {
                int ll = l0 + (k - 3);
                float vx = (ll >= 0 && ll < Ln) ? oc[ll] : 0.f;
                int l2 = ll + 1;
                float vy = (l2 >= 0 && l2 < Ln) ? oc[l2] : 0.f;
                a0 += vx * ks[k * 64 + 2 * jj];
                a1 += vy * ks[k * 64 + 2 * jj + 1];
            }
        }
        a0 = a0 >= 0.f ? a0 : a * a0;
        a1 = a1 >= 0.f ? a1 : a * a1;
        hs[c * 64 + 2 * jj]     = a0;
        hs[c * 64 + 2 * jj + 1] = a1;
        s0 += a0; q0 += a0 * a0;
        s1 += a1; q1 += a1 * a1;
    }
    psum[cg * 64 + 2 * jj]     = s0;
    psum[cg * 64 + 2 * jj + 1] = s1;
    psq[cg * 64 + 2 * jj]      = q0;
    psq[cg * 64 + 2 * jj + 1]  = q1;
    __syncthreads();
    if (t < 64) {
        float S = 0.f, Q = 0.f;
#pragma unroll
        for (int i = 0; i < 8; i++) { S += psum[i * 64 + t]; Q += psq[i * 64 + t]; }
        float m = S * (1.f / Cn);
        mres[t] = m; rres[t] = rsqrtf(Q * (1.f / Cn) - m * m + EPSf);
    }
    __syncthreads();
    float m0 = mres[2 * jj], r0 = rres[2 * jj];
    float m1 = mres[2 * jj + 1], r1 = rres[2 * jj + 1];
    float* hb = h + ((size_t)b * Cn) * Ln + lbase;
#pragma unroll 4
    for (int i = 0; i < 32; i++) {
        int c = cg * 32 + i;
        float gg = g[c], bb = bta[c];
        float2 v;
        v.x = (hs[c * 64 + 2 * jj]     - m0) * r0 * gg + bb;
        v.y = (hs[c * 64 + 2 * jj + 1] - m1) * r1 * gg + bb;
        *(float2*)&hb[(size_t)c * Ln + 2 * jj] = v;
    }
}

// ---------------- HMMA bf16-split GEMM (R9 version) -------------------------
// Y[0..255][lbase..lbase+64) = W(mat) @ X via mma.sync m16n8k16, bf16 2-way
// split (hi*hi + hi*lo + lo*hi), fp32 accumulate.
// CTA: 256 threads = 8 warps, warp tile 64(M) x 32(N); K=256 in 4 chunks of 64.
// launch_bounds(256,2): cap regs at 128 so 2 CTAs co-reside per SM.
// mode 0: Y = D   1: Y = D + R   2: Y += D   3: Y = relu(D), X prelu'd on load.
__global__ __launch_bounds__(256, 2) void gemm_mma(
    const float* __restrict__ X, const float* __restrict__ R,
    float* __restrict__ Y, int mat, const float* __restrict__ pa, int mode)
{
    extern __shared__ char smem[];
    uint16_t* Ahi = (uint16_t*)smem;          // 256 x 72
    uint16_t* Alo = Ahi + 256 * 72;           // 256 x 72
    uint16_t* Bhi = Alo + 256 * 72;           // 64 x 72  (rows = positions)
    uint16_t* Blo = Bhi + 64 * 72;            // 64 x 72

    int t = threadIdx.x, lid = t & 31, wid = t >> 5;
    int wm = wid >> 1, wn = wid & 1;          // 4 M-warps x 2 N-warps
    int b = blockIdx.y, lbase = blockIdx.x * 64;

    const float* Xb = X + (size_t)b * Cn * Ln + lbase;
    float aP = (mode == 3) ? *pa : 0.f;

    const __nv_bfloat16* Whb = g_whi + (size_t)mat * WELEM;
    const __nv_bfloat16* Wlb = g_wlo + (size_t)mat * WELEM;

    float acc[4][4][4];
#pragma unroll
    for (int i = 0; i < 4; i++)
#pragma unroll
        for (int jx = 0; jx < 4; jx++)
#pragma unroll
            for (int p = 0; p < 4; p++) acc[i][jx][p] = 0.f;

    int lr   = (lid & 7) + ((lid >> 3) & 1) * 8;   // ldmatrix row-within-16
    int koff = (lid >> 4) * 8;                      // ldmatrix k-offset
    uint32_t sbase = smem_u32(smem);

    for (int kc = 0; kc < 4; kc++) {
        // ---- stage A: 256 rows x 64 k (hi+lo), 2048 float4 each ----
        {
            const float4* shi = (const float4*)(Whb + kc * 16384);
            const float4* slo = (const float4*)(Wlb + kc * 16384);
#pragma unroll
            for (int m = 0; m < 8; m++) {
                int i = m * 256 + t;
                int row = i >> 3, q = i & 7;
                *(float4*)(Ahi + row * 72 + q * 8) = shi[i];
                *(float4*)(Alo + row * 72 + q * 8) = slo[i];
            }
        }
        // ---- stage B: X^T chunk, 64 k x 64 pos, bf16 split ----
        {
            int pos = t & 63, kp = t >> 6;
#pragma unroll
            for (int it = 0; it < 8; it++) {
                int k2 = (kp + it * 4) * 2;
                float x0 = Xb[(size_t)(kc * 64 + k2) * Ln + pos];
                float x1 = Xb[(size_t)(kc * 64 + k2 + 1) * Ln + pos];
                if (mode == 3) {
                    x0 = x0 >= 0.f ? x0 : aP * x0;
                    x1 = x1 >= 0.f ? x1 : aP * x1;
                }
                __nv_bfloat16 h0 = __float2bfloat16_rn(x0);
                __nv_bfloat16 h1 = __float2bfloat16_rn(x1);
                float r0 = x0 - __bfloat162float(h0);
                float r1 = x1 - __bfloat162float(h1);
                *(uint32_t*)(Bhi + pos * 72 + k2) =
                    (uint32_t)__bfloat16_as_ushort(h0)
                  | ((uint32_t)__bfloat16_as_ushort(h1) << 16);
                *(uint32_t*)(Blo + pos * 72 + k2) = pack_bf16x2(r0, r1);
            }
        }
        __syncthreads();

        // ---- mma over 4 k-steps of 16 ----
#pragma unroll
        for (int ks = 0; ks < 4; ks++) {
            int kcol = ks * 16 + koff;
            uint32_t bh0[4], bh1[4], bl0[4], bl1[4];
            {
                uint32_t a0 = sbase + 2 * (2 * 256 * 72) /*Bhi byte off*/;
                uint32_t ab = a0 + (uint32_t)(((wn * 32 + lr) * 72 + kcol) * 2);
                uint32_t ab2 = a0 + (uint32_t)(((wn * 32 + 16 + lr) * 72 + kcol) * 2);
                ldm4(bh0, ab);
                ldm4(bh1, ab2);
                uint32_t l0 = a0 + 64 * 72 * 2;
                ldm4(bl0, l0 + (uint32_t)(((wn * 32 + lr) * 72 + kcol) * 2));
                ldm4(bl1, l0 + (uint32_t)(((wn * 32 + 16 + lr) * 72 + kcol) * 2));
            }
#pragma unroll
            for (int mt = 0; mt < 4; mt++) {
                uint32_t ah[4], al[4];
                int arow = wm * 64 + mt * 16 + lr;
                ldm4(ah, sbase + (uint32_t)((arow * 72 + kcol) * 2));
                ldm4(al, sbase + 256 * 72 * 2 + (uint32_t)((arow * 72 + kcol) * 2));
                mma16816(acc[mt][0], ah, bh0[0], bh0[2]);
                mma16816(acc[mt][0], ah, bl0[0], bl0[2]);
                mma16816(acc[mt][0], al, bh0[0], bh0[2]);
                mma16816(acc[mt][1], ah, bh0[1], bh0[3]);
                mma16816(acc[mt][1], ah, bl0[1], bl0[3]);
                mma16816(acc[mt][1], al, bh0[1], bh0[3]);
                mma16816(acc[mt][2], ah, bh1[0], bh1[2]);
                mma16816(acc[mt][2], ah, bl1[0], bl1[2]);
                mma16816(acc[mt][2], al, bh1[0], bh1[2]);
                mma16816(acc[mt][3], ah, bh1[1], bh1[3]);
                mma16816(acc[mt][3], ah, bl1[1], bl1[3]);
                mma16816(acc[mt][3], al, bh1[1], bh1[3]);
            }
        }
        __syncthreads();
    }

    // ---- epilogue: direct float2 stores ----
    int rbase = wm * 64 + (lid >> 2);
    int cbase = wn * 32 + (lid & 3) * 2;
#pragma unroll
    for (int mt = 0; mt < 4; mt++) {
#pragma unroll
        for (int nt = 0; nt < 4; nt++) {
            int c0 = cbase + nt * 8;
#pragma unroll
            for (int half = 0; half < 2; half++) {
                int r0 = rbase + mt * 16 + half * 8;
                float vx = acc[mt][nt][half * 2 + 0];
                float vy = acc[mt][nt][half * 2 + 1];
                float* yp = Y + ((size_t)(b * Cn + r0)) * Ln + lbase + c0;
                if (mode == 1) {
                    const float2 rv = *(const float2*)
                        (R + ((size_t)(b * Cn + r0)) * Ln + lbase + c0);
                    vx += rv.x; vy += rv.y;
                } else if (mode == 2) {
                    float2 cur = *(float2*)yp;
                    vx += cur.x; vy += cur.y;
                } else if (mode == 3) {
                    vx = fmaxf(vx, 0.f); vy = fmaxf(vy, 0.f);
                }
                float2 o; o.x = vx; o.y = vy;
                *(float2*)yp = o;
            }
        }
    }
}

// ---------------- launcher ---------------------------------------------------
extern "C" void kernel_launch(void* const* d_in, const int* in_sizes, int n_in,
                              void* d_out, int out_size)
{
    const float* x           = (const float*)d_in[0];
    const float* init_ln_g   = (const float*)d_in[1];
    const float* init_ln_b   = (const float*)d_in[2];
    const float* init_conv_w = (const float*)d_in[3];
    const float* w_reduce    = (const float*)d_in[4];
    const float* w_span      = (const float*)d_in[5];
    const float* prelu_a     = (const float*)d_in[6];
    const float* ln_g        = (const float*)d_in[7];
    const float* ln_b        = (const float*)d_in[8];
    const float* conv_main_w = (const float*)d_in[9];
    const float* conv_skip_w = (const float*)d_in[10];
    const float* post_prelu  = (const float*)d_in[11];
    const float* post_conv_w = (const float*)d_in[12];

    float *buf0, *buf1, *hbuf, *skip, *kern, *tmp;
    cudaGetSymbolAddress((void**)&buf0, g_buf0);
    cudaGetSymbolAddress((void**)&buf1, g_buf1);
    cudaGetSymbolAddress((void**)&hbuf, g_h);
    cudaGetSymbolAddress((void**)&skip, g_skip);
    cudaGetSymbolAddress((void**)&kern, g_kern);
    cudaGetSymbolAddress((void**)&tmp,  g_tmp);

    cudaFuncSetAttribute(gemm_mma, cudaFuncAttributeMaxDynamicSharedMemorySize,
                         GEMM_SMEM);
    cudaFuncSetAttribute(invo_kernel, cudaFuncAttributeMaxDynamicSharedMemorySize,
                         INVO_SMEM);

    dim3 g32(Ln / 32, Bn);
    dim3 g64(Ln / 64, Bn);
    size_t nelem = (size_t)Bn * Cn * Ln;

    zero_kernel<<<(int)((nelem + 1023) / 1024), 1024>>>(skip, nelem);
    prep_kernel<<<dim3(NMAT, 8), 256>>>(conv_main_w, conv_skip_w,
                                        init_conv_w, post_conv_w);
    prep_wr<<<Nn, 256>>>(w_reduce);
    ln_kernel<<<g32, 256>>>(x, init_ln_g, init_ln_b, tmp);

    // init conv: mat 48, mode 0
    gemm_mma<<<g64, 256, GEMM_SMEM>>>(tmp, nullptr, buf0, 48, nullptr, 0);

    float* out  = buf0;
    float* outn = buf1;
    for (int i = 0; i < Nn; i++) {
        int d = 1 << (i & 7);
        kern_mma<<<g64, 256, KERN_SMEM>>>(out, w_span + (size_t)i * Kn * CRn,
                                          i, kern);
        invo_kernel<<<g64, 256, INVO_SMEM>>>(out, kern, prelu_a + i,
                                  ln_g + (size_t)i * Cn, ln_b + (size_t)i * Cn, d, hbuf);
        gemm_mma<<<g64, 256, GEMM_SMEM>>>(hbuf, out, outn, i, nullptr, 1);
        gemm_mma<<<g64, 256, GEMM_SMEM>>>(hbuf, nullptr, skip, 24 + i, nullptr, 2);
        float* tsw = out; out = outn; outn = tsw;
    }

    // post: prelu -> conv -> relu
    gemm_mma<<<g64, 256, GEMM_SMEM>>>(skip, nullptr, (float*)d_out, 49, post_prelu, 3);
}

// round 14
// speedup vs baseline: 1.6433x; 1.0664x over previous
#include <cuda_runtime.h>
#include <cuda_bf16.h>
#include <cstddef>
#include <cstdint>

#define Bn 4
#define Cn 256
#define Ln 8000
#define CRn 64
#define Kn 7
#define Nn 24
#define EPSf 1e-5f

#define NMAT 50              // 24 main + 24 skip + init(48) + post(49)
#define WELEM 65536          // 256x256 weights per matrix
#define GEMM_SMEM 55296      // A 128x72 hi+lo + B 64x72 hi+lo (bytes)
#define KERN_SMEM 36864

// ---------------- scratch (device globals; no allocation allowed) ----------
__device__ float g_buf0[(size_t)Bn * Cn * Ln];
__device__ float g_buf1[(size_t)Bn * Cn * Ln];
__device__ float g_h[(size_t)Bn * Cn * Ln];
__device__ float g_skip[(size_t)Bn * Cn * Ln];
__device__ float g_kern[(size_t)Bn * Kn * Ln];
__device__ float g_tmp[(size_t)Bn * Cn * Ln];
__device__ __nv_bfloat16 g_whi[(size_t)NMAT * WELEM];
__device__ __nv_bfloat16 g_wlo[(size_t)NMAT * WELEM];
__device__ __nv_bfloat16 g_wrhi[(size_t)Nn * CRn * Cn];
__device__ __nv_bfloat16 g_wrlo[(size_t)Nn * CRn * Cn];

// ---------------- small helpers ---------------------------------------------
__device__ __forceinline__ uint32_t smem_u32(const void* p) {
    uint32_t a;
    asm("{ .reg .u64 t; cvta.to.shared.u64 t, %1; cvt.u32.u64 %0, t; }"
        : "=r"(a) : "l"(p));
    return a;
}
__device__ __forceinline__ void ldm4(uint32_t* r, uint32_t addr) {
    asm volatile("ldmatrix.sync.aligned.m8n8.x4.shared.b16 {%0,%1,%2,%3}, [%4];"
                 : "=r"(r[0]), "=r"(r[1]), "=r"(r[2]), "=r"(r[3]) : "r"(addr));
}
__device__ __forceinline__ void mma16816(float* c, const uint32_t* a,
                                         uint32_t b0, uint32_t b1) {
    asm volatile(
        "mma.sync.aligned.m16n8k16.row.col.f32.bf16.bf16.f32 "
        "{%0,%1,%2,%3}, {%4,%5,%6,%7}, {%8,%9}, {%10,%11,%12,%13};"
        : "=f"(c[0]), "=f"(c[1]), "=f"(c[2]), "=f"(c[3])
        : "r"(a[0]), "r"(a[1]), "r"(a[2]), "r"(a[3]), "r"(b0), "r"(b1),
          "f"(c[0]), "f"(c[1]), "f"(c[2]), "f"(c[3]));
}
__device__ __forceinline__ uint32_t pack_bf16x2(float x0, float x1) {
    __nv_bfloat16 h0 = __float2bfloat16_rn(x0);
    __nv_bfloat16 h1 = __float2bfloat16_rn(x1);
    return (uint32_t)__bfloat16_as_ushort(h0)
         | ((uint32_t)__bfloat16_as_ushort(h1) << 16);
}

// ---------------- weight prep: fp32 -> bf16 hi/lo tiles ---------------------
// layout per matrix: idx = kc*16384 + row*64 + kk, W element [row][kc*64+kk]
__global__ __launch_bounds__(256) void prep_kernel(
    const float* __restrict__ mw, const float* __restrict__ swp,
    const float* __restrict__ iw, const float* __restrict__ pw)
{
    int mat = blockIdx.x, seg = blockIdx.y;
    const float* W = (mat < 24) ? mw + (size_t)mat * Cn * Cn
                   : (mat < 48) ? swp + (size_t)(mat - 24) * Cn * Cn
                   : (mat == 48) ? iw : pw;
    size_t base = (size_t)mat * WELEM;
    for (int idx = seg * 8192 + threadIdx.x; idx < (seg + 1) * 8192; idx += 256) {
        int kk = idx & 63, row = (idx >> 6) & 255, kc = idx >> 14;
        float w = W[(size_t)row * Cn + kc * 64 + kk];
        __nv_bfloat16 hi = __float2bfloat16_rn(w);
        __nv_bfloat16 lo = __float2bfloat16_rn(w - __bfloat162float(hi));
        g_whi[base + idx] = hi;
        g_wlo[base + idx] = lo;
    }
}

// wr prep: per matrix 64x256, layout idx = kc*4096 + row*64 + kk
__global__ __launch_bounds__(256) void prep_wr(const float* __restrict__ wr_all)
{
    int mat = blockIdx.x;
    const float* W = wr_all + (size_t)mat * CRn * Cn;
    size_t base = (size_t)mat * CRn * Cn;
    for (int idx = threadIdx.x; idx < CRn * Cn; idx += 256) {
        int kk = idx & 63, row = (idx >> 6) & 63, kc = idx >> 12;
        float w = W[(size_t)row * Cn + kc * 64 + kk];
        __nv_bfloat16 hi = __float2bfloat16_rn(w);
        __nv_bfloat16 lo = __float2bfloat16_rn(w - __bfloat162float(hi));
        g_wrhi[base + idx] = hi;
        g_wrlo[base + idx] = lo;
    }
}

// ---------------- channel LayerNorm (over C) --------------------------------
__global__ __launch_bounds__(256) void ln_kernel(
    const float* __restrict__ x, const float* __restrict__ g,
    const float* __restrict__ bta, float* __restrict__ y)
{
    int b = blockIdx.y, lbase = blockIdx.x * 32;
    int t = threadIdx.x, j = t & 31, cg = t >> 5;
    __shared__ float vs[Cn][32];
    __shared__ float psum[8][32], psq[8][32];
    __shared__ float mres[32], rres[32];

    const float* xb = x + ((size_t)b * Cn) * Ln + lbase;
    float s = 0.f, sq = 0.f;
#pragma unroll 4
    for (int i = 0; i < 32; i++) {
        int c = cg * 32 + i;
        float v = xb[(size_t)c * Ln + j];
        vs[c][j] = v; s += v; sq += v * v;
    }
    psum[cg][j] = s; psq[cg][j] = sq;
    __syncthreads();
    if (t < 32) {
        float S = 0.f, Q = 0.f;
#pragma unroll
        for (int i = 0; i < 8; i++) { S += psum[i][t]; Q += psq[i][t]; }
        float m = S * (1.f / Cn);
        float var = Q * (1.f / Cn) - m * m;
        mres[t] = m; rres[t] = rsqrtf(var + EPSf);
    }
    __syncthreads();
    float m = mres[j], r = rres[j];
    float* yb = y + ((size_t)b * Cn) * Ln + lbase;
#pragma unroll 4
    for (int i = 0; i < 32; i++) {
        int c = cg * 32 + i;
        yb[(size_t)c * Ln + j] = (vs[c][j] - m) * r * g[c] + bta[c];
    }
}

// ---------------- involution kernel generator (HMMA) ------------------------
__global__ __launch_bounds__(256) void kern_mma(
    const float* __restrict__ out, const float* __restrict__ ws,
    int mat, float* __restrict__ kern)
{
    extern __shared__ char ksm[];
    uint16_t* Ahi = (uint16_t*)ksm;        // 64 x 72
    uint16_t* Alo = Ahi + 64 * 72;         // 64 x 72
    uint16_t* Bhi = Alo + 64 * 72;         // 64 x 72 (rows = positions)
    uint16_t* Blo = Bhi + 64 * 72;         // 64 x 72
    float* rs = (float*)ksm;               // aliased after mma: 64 x 65

    int t = threadIdx.x, lid = t & 31, wid = t >> 5;
    int wm = wid >> 2, wn = wid & 3;       // 2 M-warps x 4 N-warps
    int b = blockIdx.y, lbase = blockIdx.x * 64;
    const float* Xb = out + (size_t)b * Cn * Ln + lbase;
    const __nv_bfloat16* Wh = g_wrhi + (size_t)mat * CRn * Cn;
    const __nv_bfloat16* Wl = g_wrlo + (size_t)mat * CRn * Cn;

    float acc[2][2][4];
#pragma unroll
    for (int i = 0; i < 2; i++)
#pragma unroll
        for (int jx = 0; jx < 2; jx++)
#pragma unroll
            for (int p = 0; p < 4; p++) acc[i][jx][p] = 0.f;

    int lr   = (lid & 7) + ((lid >> 3) & 1) * 8;
    int koff = (lid >> 4) * 8;
    uint32_t sbase = smem_u32(ksm);

    for (int kc = 0; kc < 4; kc++) {
        {
            const float4* shi = (const float4*)(Wh + kc * 4096);
            const float4* slo = (const float4*)(Wl + kc * 4096);
#pragma unroll
            for (int m = 0; m < 2; m++) {
                int i = m * 256 + t;
                int row = i >> 3, q = i & 7;
                *(float4*)(Ahi + row * 72 + q * 8) = shi[i];
                *(float4*)(Alo + row * 72 + q * 8) = slo[i];
            }
        }
        {
            int pos = t & 63, kp = t >> 6;
#pragma unroll
            for (int it = 0; it < 8; it++) {
                int k2 = (kp + it * 4) * 2;
                float x0 = Xb[(size_t)(kc * 64 + k2) * Ln + pos];
                float x1 = Xb[(size_t)(kc * 64 + k2 + 1) * Ln + pos];
                __nv_bfloat16 h0 = __float2bfloat16_rn(x0);
                __nv_bfloat16 h1 = __float2bfloat16_rn(x1);
                *(uint32_t*)(Bhi + pos * 72 + k2) =
                    (uint32_t)__bfloat16_as_ushort(h0)
                  | ((uint32_t)__bfloat16_as_ushort(h1) << 16);
                *(uint32_t*)(Blo + pos * 72 + k2) =
                    pack_bf16x2(x0 - __bfloat162float(h0),
                                x1 - __bfloat162float(h1));
            }
        }
        __syncthreads();

#pragma unroll
        for (int ks = 0; ks < 4; ks++) {
            int kcol = ks * 16 + koff;
            uint32_t bh[4], bl[4];
            uint32_t bb = sbase + 2 * (2 * 64 * 72);
            ldm4(bh, bb + (uint32_t)(((wn * 16 + lr) * 72 + kcol) * 2));
            ldm4(bl, bb + 64 * 72 * 2
                     + (uint32_t)(((wn * 16 + lr) * 72 + kcol) * 2));
#pragma unroll
            for (int mt = 0; mt < 2; mt++) {
                uint32_t ah[4], al[4];
                int arow = wm * 32 + mt * 16 + lr;
                ldm4(ah, sbase + (uint32_t)((arow * 72 + kcol) * 2));
                ldm4(al, sbase + 64 * 72 * 2
                         + (uint32_t)((arow * 72 + kcol) * 2));
                mma16816(acc[mt][0], ah, bh[0], bh[2]);
                mma16816(acc[mt][0], ah, bl[0], bl[2]);
                mma16816(acc[mt][0], al, bh[0], bh[2]);
                mma16816(acc[mt][1], ah, bh[1], bh[3]);
                mma16816(acc[mt][1], ah, bl[1], bl[3]);
                mma16816(acc[mt][1], al, bh[1], bh[3]);
            }
        }
        __syncthreads();
    }

    {
        int r0 = wm * 32 + (lid >> 2), c0 = wn * 16 + (lid & 3) * 2;
#pragma unroll
        for (int mt = 0; mt < 2; mt++)
#pragma unroll
            for (int nt = 0; nt < 2; nt++)
#pragma unroll
                for (int half = 0; half < 2; half++) {
                    int r = r0 + mt * 16 + half * 8;
                    int c = c0 + nt * 8;
                    rs[r * 65 + c]     = fmaxf(acc[mt][nt][half * 2 + 0], 0.f);
                    rs[r * 65 + c + 1] = fmaxf(acc[mt][nt][half * 2 + 1], 0.f);
                }
    }
    __syncthreads();

    for (int kk = t; kk < Kn * 64; kk += 256) {
        int k = kk >> 6, j = kk & 63;
        float a = 0.f;
        const float* wsk = ws + (size_t)k * CRn;
#pragma unroll 8
        for (int r2 = 0; r2 < CRn; r2++) a += wsk[r2] * rs[r2 * 65 + j];
        kern[((size_t)b * Kn + k) * Ln + lbase + j] = a;
    }
}

// ---------------- involution apply + PReLU + channel LN (R9 v1) -------------
__global__ __launch_bounds__(256) void invo_kernel(
    const float* __restrict__ out, const float* __restrict__ kern,
    const float* __restrict__ pa, const float* __restrict__ g,
    const float* __restrict__ bta, int dil, float* __restrict__ h)
{
    int b = blockIdx.y, lbase = blockIdx.x * 32;
    int t = threadIdx.x, j = t & 31, cg = t >> 5;
    __shared__ float ks[Kn][32];
    __shared__ float hs[Cn][32];
    __shared__ float psum[8][32], psq[8][32], mres[32], rres[32];

    if (t < Kn * 32) {
        int k = t >> 5;
        ks[k][t & 31] = kern[((size_t)b * Kn + k) * Ln + lbase + (t & 31)];
    }
    __syncthreads();

    float a = *pa;
    const float* ob = out + ((size_t)b * Cn) * Ln;
    int l = lbase + j;
    float s = 0.f, sq = 0.f;
#pragma unroll 2
    for (int i = 0; i < 32; i++) {
        int c = cg * 32 + i;
        const float* oc = ob + (size_t)c * Ln;
        float acc = 0.f;
#pragma unroll
        for (int k = 0; k < Kn; k++) {
            int ll = l + (k - 3) * dil;
            float v = (ll >= 0 && ll < Ln) ? oc[ll] : 0.f;
            acc += v * ks[k][j];
        }
        acc = acc >= 0.f ? acc : a * acc;
        hs[c][j] = acc; s += acc; sq += acc * acc;
    }
    psum[cg][j] = s; psq[cg][j] = sq;
    __syncthreads();
    if (t < 32) {
        float S = 0.f, Q = 0.f;
#pragma unroll
        for (int i = 0; i < 8; i++) { S += psum[i][t]; Q += psq[i][t]; }
        float m = S * (1.f / Cn);
        mres[t] = m; rres[t] = rsqrtf(Q * (1.f / Cn) - m * m + EPSf);
    }
    __syncthreads();
    float m = mres[j], rr = rres[j];
    float* hb = h + ((size_t)b * Cn) * Ln + lbase;
#pragma unroll 4
    for (int i = 0; i < 32; i++) {
        int c = cg * 32 + i;
        hb[(size_t)c * Ln + j] = (hs[c][j] - m) * rr * g[c] + bta[c];
    }
}

// ---------------- HMMA bf16-split GEMM, 128-thread CTA, M-tile 128 ----------
// Y[mh*128 .. +128)[lbase .. +64) = W(mat) @ X via mma.sync m16n8k16, bf16
// 2-way split (hi*hi + hi*lo + lo*hi), fp32 accumulate.
// CTA: 128 threads = 4 warps (2M x 2N), warp tile 64(M) x 32(N);
// K=256 in 4 chunks of 64. launch_bounds(128,4): 4 CTAs/SM for phase overlap.
// mode 0: Y = D   1: Y = D + R   2: Y += D   3: Y = relu(D), X prelu'd on load.
__global__ __launch_bounds__(128, 4) void gemm_mma(
    const float* __restrict__ X, const float* __restrict__ R,
    float* __restrict__ Y, int mat, const float* __restrict__ pa, int mode)
{
    extern __shared__ char smem[];
    uint16_t* Ahi = (uint16_t*)smem;          // 128 x 72
    uint16_t* Alo = Ahi + 128 * 72;           // 128 x 72
    uint16_t* Bhi = Alo + 128 * 72;           // 64 x 72  (rows = positions)
    uint16_t* Blo = Bhi + 64 * 72;            // 64 x 72

    int t = threadIdx.x, lid = t & 31, wid = t >> 5;
    int wm = wid >> 1, wn = wid & 1;          // 2 M-warps x 2 N-warps
    int mh = blockIdx.y, b = blockIdx.z;
    int lbase = blockIdx.x * 64;

    const float* Xb = X + (size_t)b * Cn * Ln + lbase;
    float aP = (mode == 3) ? *pa : 0.f;

    const __nv_bfloat16* Whb = g_whi + (size_t)mat * WELEM;
    const __nv_bfloat16* Wlb = g_wlo + (size_t)mat * WELEM;

    float acc[4][4][4];
#pragma unroll
    for (int i = 0; i < 4; i++)
#pragma unroll
        for (int jx = 0; jx < 4; jx++)
#pragma unroll
            for (int p = 0; p < 4; p++) acc[i][jx][p] = 0.f;

    int lr   = (lid & 7) + ((lid >> 3) & 1) * 8;   // ldmatrix row-within-16
    int koff = (lid >> 4) * 8;                      // ldmatrix k-offset
    uint32_t sbase = smem_u32(smem);

    for (int kc = 0; kc < 4; kc++) {
        // ---- stage A: 128 rows x 64 k (hi+lo), 1024 float4 each ----
        {
            const float4* shi = (const float4*)(Whb + kc * 16384) + mh * 1024;
            const float4* slo = (const float4*)(Wlb + kc * 16384) + mh * 1024;
#pragma unroll
            for (int m = 0; m < 8; m++) {
                int i = m * 128 + t;
                int row = i >> 3, q = i & 7;
                *(float4*)(Ahi + row * 72 + q * 8) = shi[i];
                *(float4*)(Alo + row * 72 + q * 8) = slo[i];
            }
        }
        // ---- stage B: X^T chunk, 64 k x 64 pos, bf16 split ----
        {
            int pos = t & 63, kp = t >> 6;          // kp in {0,1}
#pragma unroll
            for (int it = 0; it < 16; it++) {
                int k2 = (kp + it * 2) * 2;         // even, 0..62
                float x0 = Xb[(size_t)(kc * 64 + k2) * Ln + pos];
                float x1 = Xb[(size_t)(kc * 64 + k2 + 1) * Ln + pos];
                if (mode == 3) {
                    x0 = x0 >= 0.f ? x0 : aP * x0;
                    x1 = x1 >= 0.f ? x1 : aP * x1;
                }
                __nv_bfloat16 h0 = __float2bfloat16_rn(x0);
                __nv_bfloat16 h1 = __float2bfloat16_rn(x1);
                float r0 = x0 - __bfloat162float(h0);
                float r1 = x1 - __bfloat162float(h1);
                *(uint32_t*)(Bhi + pos * 72 + k2) =
                    (uint32_t)__bfloat16_as_ushort(h0)
                  | ((uint32_t)__bfloat16_as_ushort(h1) << 16);
                *(uint32_t*)(Blo + pos * 72 + k2) = pack_bf16x2(r0, r1);
            }
        }
        __syncthreads();

        // ---- mma over 4 k-steps of 16 ----
#pragma unroll
        for (int ks = 0; ks < 4; ks++) {
            int kcol = ks * 16 + koff;
            uint32_t bh0[4], bh1[4], bl0[4], bl1[4];
            {
                uint32_t a0 = sbase + 2 * (2 * 128 * 72);   // Bhi byte off
                ldm4(bh0, a0 + (uint32_t)(((wn * 32 + lr) * 72 + kcol) * 2));
                ldm4(bh1, a0 + (uint32_t)(((wn * 32 + 16 + lr) * 72 + kcol) * 2));
                uint32_t l0 = a0 + 64 * 72 * 2;             // Blo byte off
                ldm4(bl0, l0 + (uint32_t)(((wn * 32 + lr) * 72 + kcol) * 2));
                ldm4(bl1, l0 + (uint32_t)(((wn * 32 + 16 + lr) * 72 + kcol) * 2));
            }
#pragma unroll
            for (int mt = 0; mt < 4; mt++) {
                uint32_t ah[4], al[4];
                int arow = wm * 64 + mt * 16 + lr;
                ldm4(ah, sbase + (uint32_t)((arow * 72 + kcol) * 2));
                ldm4(al, sbase + 128 * 72 * 2 + (uint32_t)((arow * 72 + kcol) * 2));
                mma16816(acc[mt][0], ah, bh0[0], bh0[2]);
                mma16816(acc[mt][0], ah, bl0[0], bl0[2]);
                mma16816(acc[mt][0], al, bh0[0], bh0[2]);
                mma16816(acc[mt][1], ah, bh0[1], bh0[3]);
                mma16816(acc[mt][1], ah, bl0[1], bl0[3]);
                mma16816(acc[mt][1], al, bh0[1], bh0[3]);
                mma16816(acc[mt][2], ah, bh1[0], bh1[2]);
                mma16816(acc[mt][2], ah, bl1[0], bl1[2]);
                mma16816(acc[mt][2], al, bh1[0], bh1[2]);
                mma16816(acc[mt][3], ah, bh1[1], bh1[3]);
                mma16816(acc[mt][3], ah, bl1[1], bl1[3]);
                mma16816(acc[mt][3], al, bh1[1], bh1[3]);
            }
        }
        __syncthreads();
    }

    // ---- epilogue: direct float2 stores ----
    int rbase = mh * 128 + wm * 64 + (lid >> 2);
    int cbase = wn * 32 + (lid & 3) * 2;
#pragma unroll
    for (int mt = 0; mt < 4; mt++) {
#pragma unroll
        for (int nt = 0; nt < 4; nt++) {
            int c0 = cbase + nt * 8;
#pragma unroll
            for (int half = 0; half < 2; half++) {
                int r0 = rbase + mt * 16 + half * 8;
                float vx = acc[mt][nt][half * 2 + 0];
                float vy = acc[mt][nt][half * 2 + 1];
                float* yp = Y + ((size_t)(b * Cn + r0)) * Ln + lbase + c0;
                if (mode == 1) {
                    const float2 rv = *(const float2*)
                        (R + ((size_t)(b * Cn + r0)) * Ln + lbase + c0);
                    vx += rv.x; vy += rv.y;
                } else if (mode == 2) {
                    float2 cur = *(float2*)yp;
                    vx += cur.x; vy += cur.y;
                } else if (mode == 3) {
                    vx = fmaxf(vx, 0.f); vy = fmaxf(vy, 0.f);
                }
                float2 o; o.x = vx; o.y = vy;
                *(float2*)yp = o;
            }
        }
    }
}

// ---------------- launcher ---------------------------------------------------
extern "C" void kernel_launch(void* const* d_in, const int* in_sizes, int n_in,
                              void* d_out, int out_size)
{
    const float* x           = (const float*)d_in[0];
    const float* init_ln_g   = (const float*)d_in[1];
    const float* init_ln_b   = (const float*)d_in[2];
    const float* init_conv_w = (const float*)d_in[3];
    const float* w_reduce    = (const float*)d_in[4];
    const float* w_span      = (const float*)d_in[5];
    const float* prelu_a     = (const float*)d_in[6];
    const float* ln_g        = (const float*)d_in[7];
    const float* ln_b        = (const float*)d_in[8];
    const float* conv_main_w = (const float*)d_in[9];
    const float* conv_skip_w = (const float*)d_in[10];
    const float* post_prelu  = (const float*)d_in[11];
    const float* post_conv_w = (const float*)d_in[12];

    float *buf0, *buf1, *hbuf, *skip, *kern, *tmp;
    cudaGetSymbolAddress((void**)&buf0, g_buf0);
    cudaGetSymbolAddress((void**)&buf1, g_buf1);
    cudaGetSymbolAddress((void**)&hbuf, g_h);
    cudaGetSymbolAddress((void**)&skip, g_skip);
    cudaGetSymbolAddress((void**)&kern, g_kern);
    cudaGetSymbolAddress((void**)&tmp,  g_tmp);

    cudaFuncSetAttribute(gemm_mma, cudaFuncAttributeMaxDynamicSharedMemorySize,
                         GEMM_SMEM);

    dim3 g32(Ln / 32, Bn);
    dim3 g64(Ln / 64, Bn);
    dim3 gg(Ln / 64, 2, Bn);      // x: 64-pos tile, y: M-half, z: batch

    prep_kernel<<<dim3(NMAT, 8), 256>>>(conv_main_w, conv_skip_w,
                                        init_conv_w, post_conv_w);
    prep_wr<<<Nn, 256>>>(w_reduce);
    ln_kernel<<<g32, 256>>>(x, init_ln_g, init_ln_b, tmp);

    // init conv: mat 48, mode 0
    gemm_mma<<<gg, 128, GEMM_SMEM>>>(tmp, nullptr, buf0, 48, nullptr, 0);

    float* out  = buf0;
    float* outn = buf1;
    for (int i = 0; i < Nn; i++) {
        int d = 1 << (i & 7);
        kern_mma<<<g64, 256, KERN_SMEM>>>(out, w_span + (size_t)i * Kn * CRn,
                                          i, kern);
        invo_kernel<<<g32, 256>>>(out, kern, prelu_a + i,
                                  ln_g + (size_t)i * Cn, ln_b + (size_t)i * Cn, d, hbuf);
        gemm_mma<<<gg, 128, GEMM_SMEM>>>(hbuf, out, outn, i, nullptr, 1);
        // first skip write needs no zero-init: mode 0 writes, later accumulate
        gemm_mma<<<gg, 128, GEMM_SMEM>>>(hbuf, nullptr, skip, 24 + i, nullptr,
                                         (i == 0) ? 0 : 2);
        float* tsw = out; out = outn; outn = tsw;
    }

    // post: prelu -> conv -> relu
    gemm_mma<<<gg, 128, GEMM_SMEM>>>(skip, nullptr, (float*)d_out, 49, post_prelu, 3);
}

// round 15
// speedup vs baseline: 1.6728x; 1.0180x over previous
#include <cuda_runtime.h>
#include <cuda_bf16.h>
#include <cstddef>
#include <cstdint>

#define Bn 4
#define Cn 256
#define Ln 8000
#define CRn 64
#define Kn 7
#define Nn 24
#define EPSf 1e-5f

#define NMAT 50              // 24 main + 24 skip + init(48) + post(49)
#define WELEM 65536          // 256x256 weights per matrix
#define GEMM_SMEM 55296      // A 128x72 hi+lo + B 64x72 hi+lo (bytes)
#define KERN_SMEM 36864

// ---------------- scratch (device globals; no allocation allowed) ----------
__device__ float g_buf0[(size_t)Bn * Cn * Ln];
__device__ float g_buf1[(size_t)Bn * Cn * Ln];
__device__ float g_h[(size_t)Bn * Cn * Ln];
__device__ float g_skip[(size_t)Bn * Cn * Ln];
__device__ float g_kern[(size_t)Bn * Kn * Ln];
__device__ float g_tmp[(size_t)Bn * Cn * Ln];
__device__ __nv_bfloat16 g_whi[(size_t)NMAT * WELEM];
__device__ __nv_bfloat16 g_wlo[(size_t)NMAT * WELEM];
__device__ __nv_bfloat16 g_wrhi[(size_t)Nn * CRn * Cn];
__device__ __nv_bfloat16 g_wrlo[(size_t)Nn * CRn * Cn];

// ---------------- small helpers ---------------------------------------------
__device__ __forceinline__ uint32_t smem_u32(const void* p) {
    uint32_t a;
    asm("{ .reg .u64 t; cvta.to.shared.u64 t, %1; cvt.u32.u64 %0, t; }"
        : "=r"(a) : "l"(p));
    return a;
}
__device__ __forceinline__ void ldm4(uint32_t* r, uint32_t addr) {
    asm volatile("ldmatrix.sync.aligned.m8n8.x4.shared.b16 {%0,%1,%2,%3}, [%4];"
                 : "=r"(r[0]), "=r"(r[1]), "=r"(r[2]), "=r"(r[3]) : "r"(addr));
}
__device__ __forceinline__ void mma16816(float* c, const uint32_t* a,
                                         uint32_t b0, uint32_t b1) {
    asm volatile(
        "mma.sync.aligned.m16n8k16.row.col.f32.bf16.bf16.f32 "
        "{%0,%1,%2,%3}, {%4,%5,%6,%7}, {%8,%9}, {%10,%11,%12,%13};"
        : "=f"(c[0]), "=f"(c[1]), "=f"(c[2]), "=f"(c[3])
        : "r"(a[0]), "r"(a[1]), "r"(a[2]), "r"(a[3]), "r"(b0), "r"(b1),
          "f"(c[0]), "f"(c[1]), "f"(c[2]), "f"(c[3]));
}
__device__ __forceinline__ uint32_t pack_bf16x2(float x0, float x1) {
    __nv_bfloat16 h0 = __float2bfloat16_rn(x0);
    __nv_bfloat16 h1 = __float2bfloat16_rn(x1);
    return (uint32_t)__bfloat16_as_ushort(h0)
         | ((uint32_t)__bfloat16_as_ushort(h1) << 16);
}

// ---------------- weight prep: fp32 -> bf16 hi/lo tiles ---------------------
// layout per matrix: idx = kc*16384 + row*64 + kk, W element [row][kc*64+kk]
__global__ __launch_bounds__(256) void prep_kernel(
    const float* __restrict__ mw, const float* __restrict__ swp,
    const float* __restrict__ iw, const float* __restrict__ pw)
{
    int mat = blockIdx.x, seg = blockIdx.y;
    const float* W = (mat < 24) ? mw + (size_t)mat * Cn * Cn
                   : (mat < 48) ? swp + (size_t)(mat - 24) * Cn * Cn
                   : (mat == 48) ? iw : pw;
    size_t base = (size_t)mat * WELEM;
    for (int idx = seg * 8192 + threadIdx.x; idx < (seg + 1) * 8192; idx += 256) {
        int kk = idx & 63, row = (idx >> 6) & 255, kc = idx >> 14;
        float w = W[(size_t)row * Cn + kc * 64 + kk];
        __nv_bfloat16 hi = __float2bfloat16_rn(w);
        __nv_bfloat16 lo = __float2bfloat16_rn(w - __bfloat162float(hi));
        g_whi[base + idx] = hi;
        g_wlo[base + idx] = lo;
    }
}

// wr prep: per matrix 64x256, layout idx = kc*4096 + row*64 + kk
__global__ __launch_bounds__(256) void prep_wr(const float* __restrict__ wr_all)
{
    int mat = blockIdx.x;
    const float* W = wr_all + (size_t)mat * CRn * Cn;
    size_t base = (size_t)mat * CRn * Cn;
    for (int idx = threadIdx.x; idx < CRn * Cn; idx += 256) {
        int kk = idx & 63, row = (idx >> 6) & 63, kc = idx >> 12;
        float w = W[(size_t)row * Cn + kc * 64 + kk];
        __nv_bfloat16 hi = __float2bfloat16_rn(w);
        __nv_bfloat16 lo = __float2bfloat16_rn(w - __bfloat162float(hi));
        g_wrhi[base + idx] = hi;
        g_wrlo[base + idx] = lo;
    }
}

// ---------------- channel LayerNorm (over C) --------------------------------
__global__ __launch_bounds__(256) void ln_kernel(
    const float* __restrict__ x, const float* __restrict__ g,
    const float* __restrict__ bta, float* __restrict__ y)
{
    int b = blockIdx.y, lbase = blockIdx.x * 32;
    int t = threadIdx.x, j = t & 31, cg = t >> 5;
    __shared__ float vs[Cn][32];
    __shared__ float psum[8][32], psq[8][32];
    __shared__ float mres[32], rres[32];

    const float* xb = x + ((size_t)b * Cn) * Ln + lbase;
    float s = 0.f, sq = 0.f;
#pragma unroll 4
    for (int i = 0; i < 32; i++) {
        int c = cg * 32 + i;
        float v = xb[(size_t)c * Ln + j];
        vs[c][j] = v; s += v; sq += v * v;
    }
    psum[cg][j] = s; psq[cg][j] = sq;
    __syncthreads();
    if (t < 32) {
        float S = 0.f, Q = 0.f;
#pragma unroll
        for (int i = 0; i < 8; i++) { S += psum[i][t]; Q += psq[i][t]; }
        float m = S * (1.f / Cn);
        float var = Q * (1.f / Cn) - m * m;
        mres[t] = m; rres[t] = rsqrtf(var + EPSf);
    }
    __syncthreads();
    float m = mres[j], r = rres[j];
    float* yb = y + ((size_t)b * Cn) * Ln + lbase;
#pragma unroll 4
    for (int i = 0; i < 32; i++) {
        int c = cg * 32 + i;
        yb[(size_t)c * Ln + j] = (vs[c][j] - m) * r * g[c] + bta[c];
    }
}

// ---------------- involution kernel generator (HMMA, term-major mma) --------
__global__ __launch_bounds__(256) void kern_mma(
    const float* __restrict__ out, const float* __restrict__ ws,
    int mat, float* __restrict__ kern)
{
    extern __shared__ char ksm[];
    uint16_t* Ahi = (uint16_t*)ksm;        // 64 x 72
    uint16_t* Alo = Ahi + 64 * 72;         // 64 x 72
    uint16_t* Bhi = Alo + 64 * 72;         // 64 x 72 (rows = positions)
    uint16_t* Blo = Bhi + 64 * 72;         // 64 x 72
    float* rs = (float*)ksm;               // aliased after mma: 64 x 65

    int t = threadIdx.x, lid = t & 31, wid = t >> 5;
    int wm = wid >> 2, wn = wid & 3;       // 2 M-warps x 4 N-warps
    int b = blockIdx.y, lbase = blockIdx.x * 64;
    const float* Xb = out + (size_t)b * Cn * Ln + lbase;
    const __nv_bfloat16* Wh = g_wrhi + (size_t)mat * CRn * Cn;
    const __nv_bfloat16* Wl = g_wrlo + (size_t)mat * CRn * Cn;

    float acc[2][2][4];
#pragma unroll
    for (int i = 0; i < 2; i++)
#pragma unroll
        for (int jx = 0; jx < 2; jx++)
#pragma unroll
            for (int p = 0; p < 4; p++) acc[i][jx][p] = 0.f;

    int lr   = (lid & 7) + ((lid >> 3) & 1) * 8;
    int koff = (lid >> 4) * 8;
    uint32_t sbase = smem_u32(ksm);

    for (int kc = 0; kc < 4; kc++) {
        {
            const float4* shi = (const float4*)(Wh + kc * 4096);
            const float4* slo = (const float4*)(Wl + kc * 4096);
#pragma unroll
            for (int m = 0; m < 2; m++) {
                int i = m * 256 + t;
                int row = i >> 3, q = i & 7;
                *(float4*)(Ahi + row * 72 + q * 8) = shi[i];
                *(float4*)(Alo + row * 72 + q * 8) = slo[i];
            }
        }
        {
            int pos = t & 63, kp = t >> 6;
#pragma unroll
            for (int it = 0; it < 8; it++) {
                int k2 = (kp + it * 4) * 2;
                float x0 = Xb[(size_t)(kc * 64 + k2) * Ln + pos];
                float x1 = Xb[(size_t)(kc * 64 + k2 + 1) * Ln + pos];
                __nv_bfloat16 h0 = __float2bfloat16_rn(x0);
                __nv_bfloat16 h1 = __float2bfloat16_rn(x1);
                *(uint32_t*)(Bhi + pos * 72 + k2) =
                    (uint32_t)__bfloat16_as_ushort(h0)
                  | ((uint32_t)__bfloat16_as_ushort(h1) << 16);
                *(uint32_t*)(Blo + pos * 72 + k2) =
                    pack_bf16x2(x0 - __bfloat162float(h0),
                                x1 - __bfloat162float(h1));
            }
        }
        __syncthreads();

#pragma unroll
        for (int ks = 0; ks < 4; ks++) {
            int kcol = ks * 16 + koff;
            uint32_t bh[4], bl[4];
            uint32_t bb = sbase + 2 * (2 * 64 * 72);
            ldm4(bh, bb + (uint32_t)(((wn * 16 + lr) * 72 + kcol) * 2));
            ldm4(bl, bb + 64 * 72 * 2
                     + (uint32_t)(((wn * 16 + lr) * 72 + kcol) * 2));
            uint32_t ah0[4], ah1[4], al0[4], al1[4];
            {
                int ar0 = wm * 32 + lr;
                int ar1 = ar0 + 16;
                ldm4(ah0, sbase + (uint32_t)((ar0 * 72 + kcol) * 2));
                ldm4(ah1, sbase + (uint32_t)((ar1 * 72 + kcol) * 2));
                ldm4(al0, sbase + 64 * 72 * 2 + (uint32_t)((ar0 * 72 + kcol) * 2));
                ldm4(al1, sbase + 64 * 72 * 2 + (uint32_t)((ar1 * 72 + kcol) * 2));
            }
            // term-major: hh (4), hl (4), lh (4) — same-acc distance 4
            mma16816(acc[0][0], ah0, bh[0], bh[2]);
            mma16816(acc[0][1], ah0, bh[1], bh[3]);
            mma16816(acc[1][0], ah1, bh[0], bh[2]);
            mma16816(acc[1][1], ah1, bh[1], bh[3]);

            mma16816(acc[0][0], ah0, bl[0], bl[2]);
            mma16816(acc[0][1], ah0, bl[1], bl[3]);
            mma16816(acc[1][0], ah1, bl[0], bl[2]);
            mma16816(acc[1][1], ah1, bl[1], bl[3]);

            mma16816(acc[0][0], al0, bh[0], bh[2]);
            mma16816(acc[0][1], al0, bh[1], bh[3]);
            mma16816(acc[1][0], al1, bh[0], bh[2]);
            mma16816(acc[1][1], al1, bh[1], bh[3]);
        }
        __syncthreads();
    }

    {
        int r0 = wm * 32 + (lid >> 2), c0 = wn * 16 + (lid & 3) * 2;
#pragma unroll
        for (int mt = 0; mt < 2; mt++)
#pragma unroll
            for (int nt = 0; nt < 2; nt++)
#pragma unroll
                for (int half = 0; half < 2; half++) {
                    int r = r0 + mt * 16 + half * 8;
                    int c = c0 + nt * 8;
                    rs[r * 65 + c]     = fmaxf(acc[mt][nt][half * 2 + 0], 0.f);
                    rs[r * 65 + c + 1] = fmaxf(acc[mt][nt][half * 2 + 1], 0.f);
                }
    }
    __syncthreads();

    for (int kk = t; kk < Kn * 64; kk += 256) {
        int k = kk >> 6, j = kk & 63;
        float a = 0.f;
        const float* wsk = ws + (size_t)k * CRn;
#pragma unroll 8
        for (int r2 = 0; r2 < CRn; r2++) a += wsk[r2] * rs[r2 * 65 + j];
        kern[((size_t)b * Kn + k) * Ln + lbase + j] = a;
    }
}

// ---------------- involution apply + PReLU + channel LN (R9 v1) -------------
__global__ __launch_bounds__(256) void invo_kernel(
    const float* __restrict__ out, const float* __restrict__ kern,
    const float* __restrict__ pa, const float* __restrict__ g,
    const float* __restrict__ bta, int dil, float* __restrict__ h)
{
    int b = blockIdx.y, lbase = blockIdx.x * 32;
    int t = threadIdx.x, j = t & 31, cg = t >> 5;
    __shared__ float ks[Kn][32];
    __shared__ float hs[Cn][32];
    __shared__ float psum[8][32], psq[8][32], mres[32], rres[32];

    if (t < Kn * 32) {
        int k = t >> 5;
        ks[k][t & 31] = kern[((size_t)b * Kn + k) * Ln + lbase + (t & 31)];
    }
    __syncthreads();

    float a = *pa;
    const float* ob = out + ((size_t)b * Cn) * Ln;
    int l = lbase + j;
    float s = 0.f, sq = 0.f;
#pragma unroll 2
    for (int i = 0; i < 32; i++) {
        int c = cg * 32 + i;
        const float* oc = ob + (size_t)c * Ln;
        float acc = 0.f;
#pragma unroll
        for (int k = 0; k < Kn; k++) {
            int ll = l + (k - 3) * dil;
            float v = (ll >= 0 && ll < Ln) ? oc[ll] : 0.f;
            acc += v * ks[k][j];
        }
        acc = acc >= 0.f ? acc : a * acc;
        hs[c][j] = acc; s += acc; sq += acc * acc;
    }
    psum[cg][j] = s; psq[cg][j] = sq;
    __syncthreads();
    if (t < 32) {
        float S = 0.f, Q = 0.f;
#pragma unroll
        for (int i = 0; i < 8; i++) { S += psum[i][t]; Q += psq[i][t]; }
        float m = S * (1.f / Cn);
        mres[t] = m; rres[t] = rsqrtf(Q * (1.f / Cn) - m * m + EPSf);
    }
    __syncthreads();
    float m = mres[j], rr = rres[j];
    float* hb = h + ((size_t)b * Cn) * Ln + lbase;
#pragma unroll 4
    for (int i = 0; i < 32; i++) {
        int c = cg * 32 + i;
        hb[(size_t)c * Ln + j] = (hs[c][j] - m) * rr * g[c] + bta[c];
    }
}

// ---------------- HMMA bf16-split GEMM, 128-thread CTA, term-major mma ------
// Y[mh*128 .. +128)[lbase .. +64) = W(mat) @ X via mma.sync m16n8k16, bf16
// 2-way split (hi*hi + hi*lo + lo*hi), fp32 accumulate.
// CTA: 128 threads = 4 warps (2M x 2N), warp tile 64(M) x 32(N);
// K=256 in 4 chunks of 64. launch_bounds(128,4): 4 CTAs/SM.
// mma issued term-major per mt-pair: same-acc reuse distance 8 (no in-order
// issue stalls on dependent HMMA chains). Per-acc term order preserved
// (hh -> hl -> lh) => bit-identical accumulation vs previous rounds.
// mode 0: Y = D   1: Y = D + R   2: Y += D   3: Y = relu(D), X prelu'd on load.
__global__ __launch_bounds__(128, 4) void gemm_mma(
    const float* __restrict__ X, const float* __restrict__ R,
    float* __restrict__ Y, int mat, const float* __restrict__ pa, int mode)
{
    extern __shared__ char smem[];
    uint16_t* Ahi = (uint16_t*)smem;          // 128 x 72
    uint16_t* Alo = Ahi + 128 * 72;           // 128 x 72
    uint16_t* Bhi = Alo + 128 * 72;           // 64 x 72  (rows = positions)
    uint16_t* Blo = Bhi + 64 * 72;            // 64 x 72

    int t = threadIdx.x, lid = t & 31, wid = t >> 5;
    int wm = wid >> 1, wn = wid & 1;          // 2 M-warps x 2 N-warps
    int mh = blockIdx.y, b = blockIdx.z;
    int lbase = blockIdx.x * 64;

    const float* Xb = X + (size_t)b * Cn * Ln + lbase;
    float aP = (mode == 3) ? *pa : 0.f;

    const __nv_bfloat16* Whb = g_whi + (size_t)mat * WELEM;
    const __nv_bfloat16* Wlb = g_wlo + (size_t)mat * WELEM;

    float acc[4][4][4];
#pragma unroll
    for (int i = 0; i < 4; i++)
#pragma unroll
        for (int jx = 0; jx < 4; jx++)
#pragma unroll
            for (int p = 0; p < 4; p++) acc[i][jx][p] = 0.f;

    int lr   = (lid & 7) + ((lid >> 3) & 1) * 8;   // ldmatrix row-within-16
    int koff = (lid >> 4) * 8;                      // ldmatrix k-offset
    uint32_t sbase = smem_u32(smem);

    for (int kc = 0; kc < 4; kc++) {
        // ---- stage A: 128 rows x 64 k (hi+lo), 1024 float4 each ----
        {
            const float4* shi = (const float4*)(Whb + kc * 16384) + mh * 1024;
            const float4* slo = (const float4*)(Wlb + kc * 16384) + mh * 1024;
#pragma unroll
            for (int m = 0; m < 8; m++) {
                int i = m * 128 + t;
                int row = i >> 3, q = i & 7;
                *(float4*)(Ahi + row * 72 + q * 8) = shi[i];
                *(float4*)(Alo + row * 72 + q * 8) = slo[i];
            }
        }
        // ---- stage B: X^T chunk, 64 k x 64 pos, bf16 split ----
        {
            int pos = t & 63, kp = t >> 6;          // kp in {0,1}
#pragma unroll
            for (int it = 0; it < 16; it++) {
                int k2 = (kp + it * 2) * 2;         // even, 0..62
                float x0 = Xb[(size_t)(kc * 64 + k2) * Ln + pos];
                float x1 = Xb[(size_t)(kc * 64 + k2 + 1) * Ln + pos];
                if (mode == 3) {
                    x0 = x0 >= 0.f ? x0 : aP * x0;
                    x1 = x1 >= 0.f ? x1 : aP * x1;
                }
                __nv_bfloat16 h0 = __float2bfloat16_rn(x0);
                __nv_bfloat16 h1 = __float2bfloat16_rn(x1);
                float r0 = x0 - __bfloat162float(h0);
                float r1 = x1 - __bfloat162float(h1);
                *(uint32_t*)(Bhi + pos * 72 + k2) =
                    (uint32_t)__bfloat16_as_ushort(h0)
                  | ((uint32_t)__bfloat16_as_ushort(h1) << 16);
                *(uint32_t*)(Blo + pos * 72 + k2) = pack_bf16x2(r0, r1);
            }
        }
        __syncthreads();

        // ---- mma over 4 k-steps of 16, term-major per mt-pair ----
#pragma unroll
        for (int ks = 0; ks < 4; ks++) {
            int kcol = ks * 16 + koff;
            uint32_t bh0[4], bh1[4], bl0[4], bl1[4];
            {
                uint32_t a0 = sbase + 2 * (2 * 128 * 72);   // Bhi byte off
                ldm4(bh0, a0 + (uint32_t)(((wn * 32 + lr) * 72 + kcol) * 2));
                ldm4(bh1, a0 + (uint32_t)(((wn * 32 + 16 + lr) * 72 + kcol) * 2));
                uint32_t l0 = a0 + 64 * 72 * 2;             // Blo byte off
                ldm4(bl0, l0 + (uint32_t)(((wn * 32 + lr) * 72 + kcol) * 2));
                ldm4(bl1, l0 + (uint32_t)(((wn * 32 + 16 + lr) * 72 + kcol) * 2));
            }
#pragma unroll
            for (int mp = 0; mp < 2; mp++) {
                uint32_t ah0[4], ah1[4], al0[4], al1[4];
                {
                    int ar0 = wm * 64 + (mp * 2) * 16 + lr;
                    int ar1 = ar0 + 16;
                    ldm4(ah0, sbase + (uint32_t)((ar0 * 72 + kcol) * 2));
                    ldm4(ah1, sbase + (uint32_t)((ar1 * 72 + kcol) * 2));
                    ldm4(al0, sbase + 128 * 72 * 2 + (uint32_t)((ar0 * 72 + kcol) * 2));
                    ldm4(al1, sbase + 128 * 72 * 2 + (uint32_t)((ar1 * 72 + kcol) * 2));
                }
                float* A0 = &acc[mp * 2][0][0];
                float* A1 = &acc[mp * 2 + 1][0][0];
                // term hh: 8 mmas
                mma16816(A0 + 0,  ah0, bh0[0], bh0[2]);
                mma16816(A0 + 4,  ah0, bh0[1], bh0[3]);
                mma16816(A0 + 8,  ah0, bh1[0], bh1[2]);
                mma16816(A0 + 12, ah0, bh1[1], bh1[3]);
                mma16816(A1 + 0,  ah1, bh0[0], bh0[2]);
                mma16816(A1 + 4,  ah1, bh0[1], bh0[3]);
                mma16816(A1 + 8,  ah1, bh1[0], bh1[2]);
                mma16816(A1 + 12, ah1, bh1[1], bh1[3]);
                // term hl: 8 mmas
                mma16816(A0 + 0,  ah0, bl0[0], bl0[2]);
                mma16816(A0 + 4,  ah0, bl0[1], bl0[3]);
                mma16816(A0 + 8,  ah0, bl1[0], bl1[2]);
                mma16816(A0 + 12, ah0, bl1[1], bl1[3]);
                mma16816(A1 + 0,  ah1, bl0[0], bl0[2]);
                mma16816(A1 + 4,  ah1, bl0[1], bl0[3]);
                mma16816(A1 + 8,  ah1, bl1[0], bl1[2]);
                mma16816(A1 + 12, ah1, bl1[1], bl1[3]);
                // term lh: 8 mmas
                mma16816(A0 + 0,  al0, bh0[0], bh0[2]);
                mma16816(A0 + 4,  al0, bh0[1], bh0[3]);
                mma16816(A0 + 8,  al0, bh1[0], bh1[2]);
                mma16816(A0 + 12, al0, bh1[1], bh1[3]);
                mma16816(A1 + 0,  al1, bh0[0], bh0[2]);
                mma16816(A1 + 4,  al1, bh0[1], bh0[3]);
                mma16816(A1 + 8,  al1, bh1[0], bh1[2]);
                mma16816(A1 + 12, al1, bh1[1], bh1[3]);
            }
        }
        __syncthreads();
    }

    // ---- epilogue: direct float2 stores ----
    int rbase = mh * 128 + wm * 64 + (lid >> 2);
    int cbase = wn * 32 + (lid & 3) * 2;
#pragma unroll
    for (int mt = 0; mt < 4; mt++) {
#pragma unroll
        for (int nt = 0; nt < 4; nt++) {
            int c0 = cbase + nt * 8;
#pragma unroll
            for (int half = 0; half < 2; half++) {
                int r0 = rbase + mt * 16 + half * 8;
                float vx = acc[mt][nt][half * 2 + 0];
                float vy = acc[mt][nt][half * 2 + 1];
                float* yp = Y + ((size_t)(b * Cn + r0)) * Ln + lbase + c0;
                if (mode == 1) {
                    const float2 rv = *(const float2*)
                        (R + ((size_t)(b * Cn + r0)) * Ln + lbase + c0);
                    vx += rv.x; vy += rv.y;
                } else if (mode == 2) {
                    float2 cur = *(float2*)yp;
                    vx += cur.x; vy += cur.y;
                } else if (mode == 3) {
                    vx = fmaxf(vx, 0.f); vy = fmaxf(vy, 0.f);
                }
                float2 o; o.x = vx; o.y = vy;
                *(float2*)yp = o;
            }
        }
    }
}

// ---------------- launcher ---------------------------------------------------
extern "C" void kernel_launch(void* const* d_in, const int* in_sizes, int n_in,
                              void* d_out, int out_size)
{
    const float* x           = (const float*)d_in[0];
    const float* init_ln_g   = (const float*)d_in[1];
    const float* init_ln_b   = (const float*)d_in[2];
    const float* init_conv_w = (const float*)d_in[3];
    const float* w_reduce    = (const float*)d_in[4];
    const float* w_span      = (const float*)d_in[5];
    const float* prelu_a     = (const float*)d_in[6];
    const float* ln_g        = (const float*)d_in[7];
    const float* ln_b        = (const float*)d_in[8];
    const float* conv_main_w = (const float*)d_in[9];
    const float* conv_skip_w = (const float*)d_in[10];
    const float* post_prelu  = (const float*)d_in[11];
    const float* post_conv_w = (const float*)d_in[12];

    float *buf0, *buf1, *hbuf, *skip, *kern, *tmp;
    cudaGetSymbolAddress((void**)&buf0, g_buf0);
    cudaGetSymbolAddress((void**)&buf1, g_buf1);
    cudaGetSymbolAddress((void**)&hbuf, g_h);
    cudaGetSymbolAddress((void**)&skip, g_skip);
    cudaGetSymbolAddress((void**)&kern, g_kern);
    cudaGetSymbolAddress((void**)&tmp,  g_tmp);

    cudaFuncSetAttribute(gemm_mma, cudaFuncAttributeMaxDynamicSharedMemorySize,
                         GEMM_SMEM);

    dim3 g32(Ln / 32, Bn);
    dim3 g64(Ln / 64, Bn);
    dim3 gg(Ln / 64, 2, Bn);      // x: 64-pos tile, y: M-half, z: batch

    prep_kernel<<<dim3(NMAT, 8), 256>>>(conv_main_w, conv_skip_w,
                                        init_conv_w, post_conv_w);
    prep_wr<<<Nn, 256>>>(w_reduce);
    ln_kernel<<<g32, 256>>>(x, init_ln_g, init_ln_b, tmp);

    // init conv: mat 48, mode 0
    gemm_mma<<<gg, 128, GEMM_SMEM>>>(tmp, nullptr, buf0, 48, nullptr, 0);

    float* out  = buf0;
    float* outn = buf1;
    for (int i = 0; i < Nn; i++) {
        int d = 1 << (i & 7);
        kern_mma<<<g64, 256, KERN_SMEM>>>(out, w_span + (size_t)i * Kn * CRn,
                                          i, kern);
        invo_kernel<<<g32, 256>>>(out, kern, prelu_a + i,
                                  ln_g + (size_t)i * Cn, ln_b + (size_t)i * Cn, d, hbuf);
        gemm_mma<<<gg, 128, GEMM_SMEM>>>(hbuf, out, outn, i, nullptr, 1);
        // first skip write needs no zero-init: mode 0 writes, later accumulate
        gemm_mma<<<gg, 128, GEMM_SMEM>>>(hbuf, nullptr, skip, 24 + i, nullptr,
                                         (i == 0) ? 0 : 2);
        float* tsw = out; out = outn; outn = tsw;
    }

    // post: prelu -> conv -> relu
    gemm_mma<<<gg, 128, GEMM_SMEM>>>(skip, nullptr, (float*)d_out, 49, post_prelu, 3);
}